// round 9
// baseline (speedup 1.0000x reference)
#include <cuda_runtime.h>
#include <cuda_bf16.h>
#include <stdint.h>
#include <math.h>

// Problem constants
#define Bq   64
#define Tq   128
#define Eq   300
#define Hq   512
#define Cq   256
#define Mq   512
#define RPS  (Bq*Tq)      // rows per sequence: 8192
#define NROWS (2*RPS)     // 16384
#define G4H  (4*Hq)       // 2048
#define D2H  (2*Hq)       // 1024
#define NCTA 128          // persistent LSTM grid (64 per direction)
#define KE   304          // Eq padded to multiple of 16

// -------- scratch (static device globals; no allocation anywhere) -----------
// xW in gate-interleaved layout: [dir][row][(j>>1)*8 + gate*2 + (j&1)]
__device__ float d_xW[2][NROWS][G4H];
__device__ float d_P[NROWS][Cq];         // attention pre-activations
__device__ float d_r[2][Bq][D2H];        // pooled representations
__device__ __nv_bfloat16 d_Wb16[2][2][G4H][Hq];      // [dir][hi/lo][n][k]  Whh
// h state (bf16 hi only) in mma-A-fragment-major layout:
// [parity][dir][mblock(8)][ktile(32)][lane(32)][slot(4)]  (u32 = 2 bf16)
__device__ uint32_t d_h16f[2][2][8][32][32][4];
__device__ __nv_bfloat16 d_x16[2][NROWS][KE];        // [hi/lo] gathered embeddings
__device__ __nv_bfloat16 d_W16[2][2*G4H][KE];        // [hi/lo][dir*2048+n][k] Wih
__device__ float d_biasC[2*G4H];                     // combined Wih bias
__device__ __nv_bfloat16 d_Ho16[2][NROWS][D2H];      // [hi/lo] bf16 Hout (full precision)
__device__ __nv_bfloat16 d_S1W16[2][Cq][D2H];        // [hi/lo] S1W
__device__ unsigned g_cnt2[2];
__device__ unsigned g_epoch2[2];

// ---- fast activations (MUFU.EX2-based) --------------------------------------
__device__ __forceinline__ float fsigmoid(float x) {
    return __fdividef(1.f, 1.f + __expf(-x));
}
__device__ __forceinline__ float ftanh(float x) {
    return 1.f - __fdividef(2.f, 1.f + __expf(2.f * x));
}
__device__ __forceinline__ uint32_t pack_bf16(float a, float b, float* lo_a, float* lo_b) {
    __nv_bfloat16 ha = __float2bfloat16(a);
    __nv_bfloat16 hb = __float2bfloat16(b);
    *lo_a = a - __bfloat162float(ha);
    *lo_b = b - __bfloat162float(hb);
    return (uint32_t)__bfloat16_as_ushort(ha) | ((uint32_t)__bfloat16_as_ushort(hb) << 16);
}
__device__ __forceinline__ uint32_t pack_bf16_only(float a, float b) {
    return (uint32_t)__bfloat16_as_ushort(__float2bfloat16(a)) |
           ((uint32_t)__bfloat16_as_ushort(__float2bfloat16(b)) << 16);
}

// ---------------- init: reset barriers, seed h frag slab from h0 -------------
__global__ void init_state(const float* s1_h0, const float* s2_h0) {
    int idx = blockIdx.x * blockDim.x + threadIdx.x;
    if (idx < 2) { g_cnt2[idx] = 0; g_epoch2[idx] = 0; }
    if (idx >= 2 * 128 * (Hq / 2)) return;
    int jj  = idx % (Hq / 2);       // u32 pair index
    int j   = jj * 2;
    int m   = (idx / (Hq / 2)) % 128;
    int dir = idx / ((Hq / 2) * 128);
    int seq = m >> 6, b = m & 63;
    const float* h0 = seq ? s2_h0 : s1_h0;
    float h0a = h0[(dir * Bq + b) * Hq + j];
    float h0b = h0[(dir * Bq + b) * Hq + j + 1];
    uint32_t uhi = pack_bf16_only(h0a, h0b);
    int mb   = m >> 4;
    int kt   = j >> 4;
    int lane = (m & 7) * 4 + ((j >> 1) & 3);
    int slot = ((j & 15) >> 3) * 2 + ((m & 15) >> 3);
    d_h16f[0][dir][mb][kt][lane][slot] = uhi;
}

// ---------------- split Whh into bf16 hi/lo ----------------------------------
__global__ void prep_weights(const float* __restrict__ Whh_f,
                             const float* __restrict__ Whh_b) {
    int idx = blockIdx.x * blockDim.x + threadIdx.x;
    if (idx >= 2 * G4H * Hq) return;
    int dir = idx / (G4H * Hq);
    int r   = idx % (G4H * Hq);
    float w = (dir ? Whh_b : Whh_f)[r];
    __nv_bfloat16 hi = __float2bfloat16(w);
    __nv_bfloat16 lo = __float2bfloat16(w - __bfloat162float(hi));
    int n = r / Hq, k = r % Hq;
    d_Wb16[dir][0][n][k] = hi;
    d_Wb16[dir][1][n][k] = lo;
}

// ---------------- gather tokens + convert emb rows to bf16 hi/lo -------------
__global__ void gather_convert(const int* __restrict__ s1, const int* __restrict__ s2,
                               const float* __restrict__ emb) {
    int idx = blockIdx.x * blockDim.x + threadIdx.x;
    if (idx >= NROWS * KE) return;
    int m = idx / KE, k = idx % KE;
    int tok = (m < RPS) ? s1[m] : s2[m - RPS];
    float v = (k < Eq) ? emb[(long)tok * Eq + k] : 0.f;
    __nv_bfloat16 hi = __float2bfloat16(v);
    d_x16[0][m][k] = hi;
    d_x16[1][m][k] = __float2bfloat16(v - __bfloat162float(hi));
}

// ---------------- convert Wih (both dirs) to bf16 hi/lo + combined bias ------
__global__ void convert_wih(const float* __restrict__ Wih_f, const float* __restrict__ Wih_b,
                            const float* __restrict__ b_f, const float* __restrict__ b_b) {
    int idx = blockIdx.x * blockDim.x + threadIdx.x;
    if (idx >= 2 * G4H * KE) return;
    int n = idx / KE, k = idx % KE;
    int dir = n >> 11, nn = n & 2047;
    const float* W = dir ? Wih_b : Wih_f;
    float v = (k < Eq) ? W[(long)nn * Eq + k] : 0.f;
    __nv_bfloat16 hi = __float2bfloat16(v);
    d_W16[0][n][k] = hi;
    d_W16[1][n][k] = __float2bfloat16(v - __bfloat162float(hi));
    if (k == 0) d_biasC[n] = (dir ? b_b : b_f)[nn];
}

// ---------------- convert S1W to bf16 hi/lo -----------------------------------
__global__ void convert_s1w(const float* __restrict__ S1W) {
    int idx = blockIdx.x * blockDim.x + threadIdx.x;
    if (idx >= Cq * D2H) return;
    float v = S1W[idx];
    int c = idx / D2H, k = idx % D2H;
    __nv_bfloat16 hi = __float2bfloat16(v);
    d_S1W16[0][c][k] = hi;
    d_S1W16[1][c][k] = __float2bfloat16(v - __bfloat162float(hi));
}

// ---------------- mma.sync bf16 helper ---------------------------------------
__device__ __forceinline__ void mma_bf16(float* d, const uint32_t* a, const uint32_t* b) {
    asm volatile(
        "mma.sync.aligned.m16n8k16.row.col.f32.bf16.bf16.f32 "
        "{%0,%1,%2,%3}, {%4,%5,%6,%7}, {%8,%9}, {%0,%1,%2,%3};\n"
        : "+f"(d[0]), "+f"(d[1]), "+f"(d[2]), "+f"(d[3])
        : "r"(a[0]), "r"(a[1]), "r"(a[2]), "r"(a[3]),
          "r"(b[0]), "r"(b[1]));
}

// ---------------- xW via tensor cores: [16384,304] @ [304,4096] --------------
__global__ __launch_bounds__(256)
void xw_mma() {
    const int lane = threadIdx.x & 31;
    const int warp = threadIdx.x >> 5;
    const int wm = warp & 1, wn = warp >> 1;
    const int m0 = blockIdx.y * 64 + wm * 32;
    const int n0 = blockIdx.x * 256 + wn * 64;
    const int RS = KE / 2;                 // u32 row stride (152)
    const int kc = lane & 3;
    const int rr = lane >> 2;

    const uint32_t* Xhi = (const uint32_t*)&d_x16[0][0][0];
    const uint32_t* Xlo = (const uint32_t*)&d_x16[1][0][0];
    const uint32_t* Whi = (const uint32_t*)&d_W16[0][0][0];
    const uint32_t* Wlo = (const uint32_t*)&d_W16[1][0][0];

    float acc[2][8][4] = {};

    for (int kt = 0; kt < KE / 16; ++kt) {
        const int k0 = kt * 8;
        uint32_t aH[2][4], aL[2][4];
#pragma unroll
        for (int mt = 0; mt < 2; ++mt) {
            int base = (m0 + mt * 16 + rr) * RS + k0 + kc;
            aH[mt][0] = Xhi[base];          aH[mt][1] = Xhi[base + 8 * RS];
            aH[mt][2] = Xhi[base + 4];      aH[mt][3] = Xhi[base + 8 * RS + 4];
            aL[mt][0] = Xlo[base];          aL[mt][1] = Xlo[base + 8 * RS];
            aL[mt][2] = Xlo[base + 4];      aL[mt][3] = Xlo[base + 8 * RS + 4];
        }
#pragma unroll
        for (int nt = 0; nt < 8; ++nt) {
            int bb = (n0 + nt * 8 + rr) * RS + k0 + kc;
            uint32_t bh[2] = { Whi[bb], Whi[bb + 4] };
            uint32_t bl[2] = { Wlo[bb], Wlo[bb + 4] };
#pragma unroll
            for (int mt = 0; mt < 2; ++mt) {
                mma_bf16(acc[mt][nt], aH[mt], bh);
                mma_bf16(acc[mt][nt], aL[mt], bh);
                mma_bf16(acc[mt][nt], aH[mt], bl);
            }
        }
    }
    // write gate-interleaved: [m][(j>>1)*8 + g*2 + (j&1)]
#pragma unroll
    for (int mt = 0; mt < 2; ++mt)
#pragma unroll
        for (int nt = 0; nt < 8; ++nt) {
            int r  = m0 + mt * 16 + rr;
            int cc = n0 + nt * 8 + (lane & 3) * 2;
#pragma unroll
            for (int i = 0; i < 4; ++i) {
                int m = r + (i >> 1) * 8;
                int n = cc + (i & 1);
                int dir = n >> 11, nn = n & 2047;
                int g = nn >> 9, j = nn & 511;
                d_xW[dir][m][(j >> 1) * 8 + g * 2 + (j & 1)] = acc[mt][nt][i] + d_biasC[n];
            }
        }
}

// ---------------- persistent LSTM: all 128 steps, tensor cores ---------------
// 128 CTAs (64/dir). h bf16-hi-only in fragment-major layout (1 LDG.128/kt).
// W hi+lo in smem: 2 MMAs per gate per kt. Poll-by-all grid barrier.
__global__ __launch_bounds__(256)
void lstm_persist(const int* __restrict__ s1_len, const int* __restrict__ s2_len,
                  const float* __restrict__ s1_c0, const float* __restrict__ s2_c0) {
    extern __shared__ uint32_t sWf[];   // 64KB: [g(4)][kt(32)][lane(32)][bh0,bh1,bl0,bl1]
    const int tid  = threadIdx.x;
    const int lane = tid & 31;
    const int warp = tid >> 5;
    const int dir  = blockIdx.x & 1;
    const int j0   = (blockIdx.x >> 1) * 8;

    // ---- packed fragment-major weight fill (once) ----
    for (int i = tid; i < 4096; i += 256) {
        int g  = i >> 10;
        int kt = (i >> 5) & 31;
        int l  = i & 31;
        int n  = l >> 2;
        int k0 = kt * 16 + (l & 3) * 2;
        const uint32_t* srcH = (const uint32_t*)&d_Wb16[dir][0][g * Hq + j0 + n][0];
        const uint32_t* srcL = (const uint32_t*)&d_Wb16[dir][1][g * Hq + j0 + n][0];
        uint4 v;
        v.x = srcH[k0 >> 1];       v.y = srcH[(k0 + 8) >> 1];
        v.z = srcL[k0 >> 1];       v.w = srcL[(k0 + 8) >> 1];
        *(uint4*)&sWf[i * 4] = v;
    }

    // ---- per-thread ownership ----
    const int m0  = warp * 16;
    const int seq = m0 >> 6;
    const int r0  = m0 + (lane >> 2);
    const int c0j = j0 + (lane & 3) * 2;
    const int*   lens = seq ? s2_len : s1_len;
    const float* c0p  = seq ? s2_c0  : s1_c0;
    const int b0 = r0 & 63;
    const int len_[2] = { lens[b0], lens[b0 + 8] };
    const int ktW   = j0 >> 4;          // this CTA's k-tile in the h slab
    const int kslot = (j0 >> 3) & 1;

    float creg[4];
#pragma unroll
    for (int ri = 0; ri < 2; ++ri)
#pragma unroll
        for (int ci = 0; ci < 2; ++ci)
            creg[ri * 2 + ci] = c0p[(dir * Bq + b0 + 8 * ri) * Hq + c0j + ci];

    __syncthreads();

    unsigned myep = 0;

    for (int t = 0; t < Tq; ++t) {
        const int p = t & 1;
        const uint32_t* HhiF = &d_h16f[p][dir][warp][0][0][0];

        // ---- prefetch xW gate values (gate-interleaved: 2 x LDG.128 per ri) ----
        int rowx_[2];
        float4 pa[2], pb[2];
#pragma unroll
        for (int ri = 0; ri < 2; ++ri) {
            int b = b0 + 8 * ri;
            int len = len_[ri];
            int tpos = dir ? ((t < len) ? (len - 1 - t) : t) : t;
            rowx_[ri] = (seq * Bq + b) * Tq + tpos;
            const float4* x4 = (const float4*)&d_xW[dir][rowx_[ri]][(c0j >> 1) * 8];
            pa[ri] = __ldcs(x4);
            pb[ri] = __ldcs(x4 + 1);
        }

        float acc[4][4] = {};
        uint32_t aH[3][4];

#define LOADA(buf, ktv) {                                                         \
        uint4 vh = __ldcg((const uint4*)(HhiF + (ktv) * 128 + lane * 4));         \
        aH[buf][0] = vh.x; aH[buf][1] = vh.y; aH[buf][2] = vh.z; aH[buf][3] = vh.w; }

        LOADA(0, 0);
        LOADA(1, 1);

#pragma unroll
        for (int kt = 0; kt < 32; ++kt) {
            const int cur = kt % 3;
            if (kt < 30) { LOADA((kt + 2) % 3, kt + 2); }
#pragma unroll
            for (int g = 0; g < 4; ++g) {
                uint4 wv = *(const uint4*)&sWf[((g * 32 + kt) * 32 + lane) * 4];
                uint32_t bh[2] = { wv.x, wv.y };
                uint32_t bl[2] = { wv.z, wv.w };
                mma_bf16(acc[g], aH[cur], bh);   // h_hi * W_hi
                mma_bf16(acc[g], aH[cur], bl);   // h_hi * W_lo
            }
        }
#undef LOADA

        // ---- epilogue: gates, cell/h update, publish h ----
        uint32_t hhi[2];
#pragma unroll
        for (int ri = 0; ri < 2; ++ri) {
            const int rowx = rowx_[ri];
            float hv[2];
            // gate-interleaved: pa = {gi0,gi1,gf0,gf1}, pb = {gg0,gg1,go0,go1}
            {
                float gi = acc[0][ri * 2 + 0] + pa[ri].x;
                float gf = acc[1][ri * 2 + 0] + pa[ri].z;
                float gg = acc[2][ri * 2 + 0] + pb[ri].x;
                float go = acc[3][ri * 2 + 0] + pb[ri].z;
                float c  = fsigmoid(gf) * creg[ri * 2 + 0] + fsigmoid(gi) * ftanh(gg);
                hv[0]    = fsigmoid(go) * ftanh(c);
                creg[ri * 2 + 0] = c;
            }
            {
                float gi = acc[0][ri * 2 + 1] + pa[ri].y;
                float gf = acc[1][ri * 2 + 1] + pa[ri].w;
                float gg = acc[2][ri * 2 + 1] + pb[ri].y;
                float go = acc[3][ri * 2 + 1] + pb[ri].w;
                float c  = fsigmoid(gf) * creg[ri * 2 + 1] + fsigmoid(gi) * ftanh(gg);
                hv[1]    = fsigmoid(go) * ftanh(c);
                creg[ri * 2 + 1] = c;
            }
            float la, lb;
            hhi[ri] = pack_bf16(hv[0], hv[1], &la, &lb);
            *(uint32_t*)&d_Ho16[0][rowx][dir * Hq + c0j] = hhi[ri];
            *(uint32_t*)&d_Ho16[1][rowx][dir * Hq + c0j] = pack_bf16_only(la, lb);
        }
        // h state: one STG.64 (hi only)
        *(uint2*)&d_h16f[p ^ 1][dir][warp][ktW][lane][kslot * 2] = make_uint2(hhi[0], hhi[1]);

        // ---- per-direction grid barrier (poll-by-all) ----
        __syncthreads();
        if (tid == 0) {
            __threadfence();
            unsigned arrived = atomicAdd(&g_cnt2[dir], 1);
            if (arrived == NCTA / 2 - 1) {
                g_cnt2[dir] = 0;
                __threadfence();
                atomicExch(&g_epoch2[dir], myep + 1);
            }
        }
        while (*(volatile unsigned*)&g_epoch2[dir] <= myep) { }
        __threadfence();
        myep++;
    }
}

// ---------------- attention projection via tensor cores ----------------------
__global__ __launch_bounds__(256)
void attn_mma() {
    const int lane = threadIdx.x & 31;
    const int warp = threadIdx.x >> 5;
    const int wm = warp & 1, wn = warp >> 1;
    const int m0 = blockIdx.y * 64 + wm * 32;
    const int n0 = wn * 64;
    const int RS = D2H / 2;
    const int kc = lane & 3;
    const int rr = lane >> 2;

    const uint32_t* Xhi = (const uint32_t*)&d_Ho16[0][0][0];
    const uint32_t* Xlo = (const uint32_t*)&d_Ho16[1][0][0];
    const uint32_t* Whi = (const uint32_t*)&d_S1W16[0][0][0];
    const uint32_t* Wlo = (const uint32_t*)&d_S1W16[1][0][0];

    float acc[2][8][4] = {};

    for (int kt = 0; kt < D2H / 16; ++kt) {
        const int k0 = kt * 8;
        uint32_t aH[2][4], aL[2][4];
#pragma unroll
        for (int mt = 0; mt < 2; ++mt) {
            int base = (m0 + mt * 16 + rr) * RS + k0 + kc;
            aH[mt][0] = Xhi[base];          aH[mt][1] = Xhi[base + 8 * RS];
            aH[mt][2] = Xhi[base + 4];      aH[mt][3] = Xhi[base + 8 * RS + 4];
            aL[mt][0] = Xlo[base];          aL[mt][1] = Xlo[base + 8 * RS];
            aL[mt][2] = Xlo[base + 4];      aL[mt][3] = Xlo[base + 8 * RS + 4];
        }
#pragma unroll
        for (int nt = 0; nt < 8; ++nt) {
            int bb = (n0 + nt * 8 + rr) * RS + k0 + kc;
            uint32_t bh[2] = { Whi[bb], Whi[bb + 4] };
            uint32_t bl[2] = { Wlo[bb], Wlo[bb + 4] };
#pragma unroll
            for (int mt = 0; mt < 2; ++mt) {
                mma_bf16(acc[mt][nt], aH[mt], bh);
                mma_bf16(acc[mt][nt], aL[mt], bh);
                mma_bf16(acc[mt][nt], aH[mt], bl);
            }
        }
    }
#pragma unroll
    for (int mt = 0; mt < 2; ++mt)
#pragma unroll
        for (int nt = 0; nt < 8; ++nt) {
            int r  = m0 + mt * 16 + rr;
            int cc = n0 + nt * 8 + (lane & 3) * 2;
#pragma unroll
            for (int i = 0; i < 4; ++i)
                d_P[r + (i >> 1) * 8][cc + (i & 1)] = acc[mt][nt][i];
        }
}

// ---------------- masked softmax attention pooling ---------------------------
__global__ __launch_bounds__(128)
void attn_pool(const int* __restrict__ s1_len, const int* __restrict__ s2_len,
               const float* __restrict__ S2W) {
    __shared__ float sS2[Cq];
    __shared__ float ssc[Tq];
    __shared__ float red[Tq];
    int sb = blockIdx.x;
    int seq = sb >> 6, b = sb & 63;
    int t = threadIdx.x;
    for (int c = t; c < Cq; c += Tq) sS2[c] = S2W[c];
    __syncthreads();

    long row = (long)sb * Tq + t;
    float s = 0.f;
    for (int c = 0; c < Cq; ++c) s += ftanh(d_P[row][c]) * sS2[c];
    int len = (seq ? s2_len : s1_len)[b];
    ssc[t] = (t < len) ? s : -1e9f;
    __syncthreads();

    red[t] = ssc[t]; __syncthreads();
    for (int o = 64; o > 0; o >>= 1) { if (t < o) red[t] = fmaxf(red[t], red[t + o]); __syncthreads(); }
    float mx = red[0]; __syncthreads();
    float ex = expf(ssc[t] - mx);
    red[t] = ex; __syncthreads();
    for (int o = 64; o > 0; o >>= 1) { if (t < o) red[t] += red[t + o]; __syncthreads(); }
    float inv = 1.f / red[0];
    __syncthreads();
    ssc[t] = ex * inv;
    __syncthreads();

    long rowbase = (long)sb * Tq;
    for (int d = t; d < D2H; d += Tq) {
        float acc = 0.f;
        for (int tt = 0; tt < Tq; ++tt) {
            long rw = rowbase + tt;
            float h = __bfloat162float(d_Ho16[0][rw][d]) + __bfloat162float(d_Ho16[1][rw][d]);
            acc += ssc[tt] * h;
        }
        d_r[seq][b][d] = acc;
    }
}

// ---------------- final MLP head + sigmoid ----------------------------------
__global__ __launch_bounds__(512)
void final_mlp(const float* __restrict__ mlpW, const float* __restrict__ mlpb,
               const float* __restrict__ outW, const float* __restrict__ outb,
               float* __restrict__ out) {
    __shared__ float merged[4 * Hq];
    __shared__ float smlp[Mq];
    __shared__ float red[16];
    int b = blockIdx.x;
    int tid = threadIdx.x;

    for (int d = tid; d < 2 * D2H; d += Mq) {
        float v;
        if (d < D2H) v = d_r[0][b][d] + d_r[1][b][d];
        else { float df = d_r[0][b][d - D2H] - d_r[1][b][d - D2H]; v = df * df; }
        merged[d] = v;
    }
    __syncthreads();

    int warp = tid >> 5, lane = tid & 31;
    for (int m = warp * 32; m < warp * 32 + 32; ++m) {
        float p = 0.f;
        for (int d = lane; d < 4 * Hq; d += 32) p += merged[d] * mlpW[(long)m * 4 * Hq + d];
        for (int o = 16; o > 0; o >>= 1) p += __shfl_down_sync(0xffffffff, p, o);
        if (lane == 0) smlp[m] = p + mlpb[m];
    }
    __syncthreads();

    float p = smlp[tid] * outW[tid];
    for (int o = 16; o > 0; o >>= 1) p += __shfl_down_sync(0xffffffff, p, o);
    if (lane == 0) red[warp] = p;
    __syncthreads();
    if (tid == 0) {
        float l = outb[0];
        for (int w = 0; w < 16; ++w) l += red[w];
        out[b] = 1.f / (1.f + expf(-l));
    }
}

// ---------------- launch ------------------------------------------------------
extern "C" void kernel_launch(void* const* d_in, const int* in_sizes, int n_in,
                              void* d_out, int out_size) {
    const int*   s1     = (const int*)d_in[0];
    const int*   s2     = (const int*)d_in[1];
    const int*   s1_len = (const int*)d_in[2];
    const int*   s2_len = (const int*)d_in[3];
    const float* s1_h0  = (const float*)d_in[4];
    const float* s1_c0  = (const float*)d_in[5];
    const float* s2_h0  = (const float*)d_in[6];
    const float* s2_c0  = (const float*)d_in[7];
    const float* emb    = (const float*)d_in[8];
    const float* Wih_f  = (const float*)d_in[9];
    const float* Whh_f  = (const float*)d_in[10];
    const float* b_f    = (const float*)d_in[11];
    const float* Wih_b  = (const float*)d_in[12];
    const float* Whh_b  = (const float*)d_in[13];
    const float* b_b    = (const float*)d_in[14];
    const float* S1W    = (const float*)d_in[15];
    const float* S2W    = (const float*)d_in[16];
    const float* mlpW   = (const float*)d_in[17];
    const float* mlpb   = (const float*)d_in[18];
    const float* outW   = (const float*)d_in[19];
    const float* outb   = (const float*)d_in[20];
    float* out = (float*)d_out;

    const int smem_lstm = 16384 * (int)sizeof(uint32_t);   // 64KB
    cudaFuncSetAttribute(lstm_persist, cudaFuncAttributeMaxDynamicSharedMemorySize, smem_lstm);

    init_state<<<(2 * 128 * (Hq / 2) + 255) / 256, 256>>>(s1_h0, s2_h0);
    prep_weights<<<(2 * G4H * Hq + 255) / 256, 256>>>(Whh_f, Whh_b);
    gather_convert<<<(NROWS * KE + 255) / 256, 256>>>(s1, s2, emb);
    convert_wih<<<(2 * G4H * KE + 255) / 256, 256>>>(Wih_f, Wih_b, b_f, b_b);
    convert_s1w<<<(Cq * D2H + 255) / 256, 256>>>(S1W);

    xw_mma<<<dim3(16, 256), 256>>>();                  // both dirs fused

    lstm_persist<<<NCTA, 256, smem_lstm>>>(s1_len, s2_len, s1_c0, s2_c0);

    attn_mma<<<dim3(1, 256), 256>>>();
    attn_pool<<<128, 128>>>(s1_len, s2_len, S2W);
    final_mlp<<<Bq, 512>>>(mlpW, mlpb, outW, outb, out);
}

// round 10
// speedup vs baseline: 1.1811x; 1.1811x over previous
#include <cuda_runtime.h>
#include <cuda_bf16.h>
#include <stdint.h>
#include <math.h>

// Problem constants
#define Bq   64
#define Tq   128
#define Eq   300
#define Hq   512
#define Cq   256
#define Mq   512
#define RPS  (Bq*Tq)      // rows per sequence: 8192
#define NROWS (2*RPS)     // 16384
#define G4H  (4*Hq)       // 2048
#define D2H  (2*Hq)       // 1024
#define NCTA 128          // persistent LSTM grid (64 per direction)
#define KE   304          // Eq padded to multiple of 16

// -------- scratch (static device globals; no allocation anywhere) -----------
// xW in gate-interleaved layout: [dir][row][(j>>1)*8 + gate*2 + (j&1)]
__device__ float d_xW[2][NROWS][G4H];
__device__ float d_P[NROWS][Cq];         // attention pre-activations
__device__ float d_r[2][Bq][D2H];        // pooled representations
__device__ __nv_bfloat16 d_Wb16[2][2][G4H][Hq];      // [dir][hi/lo][n][k]  Whh
// h state (bf16 hi only) in mma-A-fragment-major layout:
// [parity][dir][mblock(8)][ktile(32)][lane(32)][slot(4)]  (u32 = 2 bf16)
__device__ uint32_t d_h16f[2][2][8][32][32][4];
__device__ __nv_bfloat16 d_x16[2][NROWS][KE];        // [hi/lo] gathered embeddings
__device__ __nv_bfloat16 d_W16[2][2*G4H][KE];        // [hi/lo][dir*2048+n][k] Wih
__device__ float d_biasC[2*G4H];                     // combined Wih bias
__device__ __nv_bfloat16 d_Ho16[2][NROWS][D2H];      // [hi/lo] bf16 Hout (full precision)
__device__ __nv_bfloat16 d_S1W16[2][Cq][D2H];        // [hi/lo] S1W
__device__ unsigned g_cnt2[2];
__device__ unsigned g_epoch2[2];

// ---- fast activations (MUFU.EX2-based) --------------------------------------
__device__ __forceinline__ float fsigmoid(float x) {
    return __fdividef(1.f, 1.f + __expf(-x));
}
__device__ __forceinline__ float ftanh(float x) {
    return 1.f - __fdividef(2.f, 1.f + __expf(2.f * x));
}
__device__ __forceinline__ uint32_t pack_bf16(float a, float b, float* lo_a, float* lo_b) {
    __nv_bfloat16 ha = __float2bfloat16(a);
    __nv_bfloat16 hb = __float2bfloat16(b);
    *lo_a = a - __bfloat162float(ha);
    *lo_b = b - __bfloat162float(hb);
    return (uint32_t)__bfloat16_as_ushort(ha) | ((uint32_t)__bfloat16_as_ushort(hb) << 16);
}
__device__ __forceinline__ uint32_t pack_bf16_only(float a, float b) {
    return (uint32_t)__bfloat16_as_ushort(__float2bfloat16(a)) |
           ((uint32_t)__bfloat16_as_ushort(__float2bfloat16(b)) << 16);
}

// ---------------- init: reset barriers, seed h frag slab from h0 -------------
__global__ void init_state(const float* s1_h0, const float* s2_h0) {
    int idx = blockIdx.x * blockDim.x + threadIdx.x;
    if (idx < 2) { g_cnt2[idx] = 0; g_epoch2[idx] = 0; }
    if (idx >= 2 * 128 * (Hq / 2)) return;
    int jj  = idx % (Hq / 2);       // u32 pair index
    int j   = jj * 2;
    int m   = (idx / (Hq / 2)) % 128;
    int dir = idx / ((Hq / 2) * 128);
    int seq = m >> 6, b = m & 63;
    const float* h0 = seq ? s2_h0 : s1_h0;
    float h0a = h0[(dir * Bq + b) * Hq + j];
    float h0b = h0[(dir * Bq + b) * Hq + j + 1];
    uint32_t uhi = pack_bf16_only(h0a, h0b);
    int mb   = m >> 4;
    int kt   = j >> 4;
    int lane = (m & 7) * 4 + ((j >> 1) & 3);
    int slot = ((j & 15) >> 3) * 2 + ((m & 15) >> 3);
    d_h16f[0][dir][mb][kt][lane][slot] = uhi;
}

// ---------------- split Whh into bf16 hi/lo ----------------------------------
__global__ void prep_weights(const float* __restrict__ Whh_f,
                             const float* __restrict__ Whh_b) {
    int idx = blockIdx.x * blockDim.x + threadIdx.x;
    if (idx >= 2 * G4H * Hq) return;
    int dir = idx / (G4H * Hq);
    int r   = idx % (G4H * Hq);
    float w = (dir ? Whh_b : Whh_f)[r];
    __nv_bfloat16 hi = __float2bfloat16(w);
    __nv_bfloat16 lo = __float2bfloat16(w - __bfloat162float(hi));
    int n = r / Hq, k = r % Hq;
    d_Wb16[dir][0][n][k] = hi;
    d_Wb16[dir][1][n][k] = lo;
}

// ---------------- gather tokens + convert emb rows to bf16 hi/lo -------------
__global__ void gather_convert(const int* __restrict__ s1, const int* __restrict__ s2,
                               const float* __restrict__ emb) {
    int idx = blockIdx.x * blockDim.x + threadIdx.x;
    if (idx >= NROWS * KE) return;
    int m = idx / KE, k = idx % KE;
    int tok = (m < RPS) ? s1[m] : s2[m - RPS];
    float v = (k < Eq) ? emb[(long)tok * Eq + k] : 0.f;
    __nv_bfloat16 hi = __float2bfloat16(v);
    d_x16[0][m][k] = hi;
    d_x16[1][m][k] = __float2bfloat16(v - __bfloat162float(hi));
}

// ---------------- convert Wih (both dirs) to bf16 hi/lo + combined bias ------
__global__ void convert_wih(const float* __restrict__ Wih_f, const float* __restrict__ Wih_b,
                            const float* __restrict__ b_f, const float* __restrict__ b_b) {
    int idx = blockIdx.x * blockDim.x + threadIdx.x;
    if (idx >= 2 * G4H * KE) return;
    int n = idx / KE, k = idx % KE;
    int dir = n >> 11, nn = n & 2047;
    const float* W = dir ? Wih_b : Wih_f;
    float v = (k < Eq) ? W[(long)nn * Eq + k] : 0.f;
    __nv_bfloat16 hi = __float2bfloat16(v);
    d_W16[0][n][k] = hi;
    d_W16[1][n][k] = __float2bfloat16(v - __bfloat162float(hi));
    if (k == 0) d_biasC[n] = (dir ? b_b : b_f)[nn];
}

// ---------------- convert S1W to bf16 hi/lo -----------------------------------
__global__ void convert_s1w(const float* __restrict__ S1W) {
    int idx = blockIdx.x * blockDim.x + threadIdx.x;
    if (idx >= Cq * D2H) return;
    float v = S1W[idx];
    int c = idx / D2H, k = idx % D2H;
    __nv_bfloat16 hi = __float2bfloat16(v);
    d_S1W16[0][c][k] = hi;
    d_S1W16[1][c][k] = __float2bfloat16(v - __bfloat162float(hi));
}

// ---------------- mma.sync bf16 helper ---------------------------------------
__device__ __forceinline__ void mma_bf16(float* d, const uint32_t* a, const uint32_t* b) {
    asm volatile(
        "mma.sync.aligned.m16n8k16.row.col.f32.bf16.bf16.f32 "
        "{%0,%1,%2,%3}, {%4,%5,%6,%7}, {%8,%9}, {%0,%1,%2,%3};\n"
        : "+f"(d[0]), "+f"(d[1]), "+f"(d[2]), "+f"(d[3])
        : "r"(a[0]), "r"(a[1]), "r"(a[2]), "r"(a[3]),
          "r"(b[0]), "r"(b[1]));
}

// ---------------- xW via tensor cores: [16384,304] @ [304,4096] --------------
__global__ __launch_bounds__(256)
void xw_mma() {
    const int lane = threadIdx.x & 31;
    const int warp = threadIdx.x >> 5;
    const int wm = warp & 1, wn = warp >> 1;
    const int m0 = blockIdx.y * 64 + wm * 32;
    const int n0 = blockIdx.x * 256 + wn * 64;
    const int RS = KE / 2;                 // u32 row stride (152)
    const int kc = lane & 3;
    const int rr = lane >> 2;

    const uint32_t* Xhi = (const uint32_t*)&d_x16[0][0][0];
    const uint32_t* Xlo = (const uint32_t*)&d_x16[1][0][0];
    const uint32_t* Whi = (const uint32_t*)&d_W16[0][0][0];
    const uint32_t* Wlo = (const uint32_t*)&d_W16[1][0][0];

    float acc[2][8][4] = {};

    for (int kt = 0; kt < KE / 16; ++kt) {
        const int k0 = kt * 8;
        uint32_t aH[2][4], aL[2][4];
#pragma unroll
        for (int mt = 0; mt < 2; ++mt) {
            int base = (m0 + mt * 16 + rr) * RS + k0 + kc;
            aH[mt][0] = Xhi[base];          aH[mt][1] = Xhi[base + 8 * RS];
            aH[mt][2] = Xhi[base + 4];      aH[mt][3] = Xhi[base + 8 * RS + 4];
            aL[mt][0] = Xlo[base];          aL[mt][1] = Xlo[base + 8 * RS];
            aL[mt][2] = Xlo[base + 4];      aL[mt][3] = Xlo[base + 8 * RS + 4];
        }
#pragma unroll
        for (int nt = 0; nt < 8; ++nt) {
            int bb = (n0 + nt * 8 + rr) * RS + k0 + kc;
            uint32_t bh[2] = { Whi[bb], Whi[bb + 4] };
            uint32_t bl[2] = { Wlo[bb], Wlo[bb + 4] };
#pragma unroll
            for (int mt = 0; mt < 2; ++mt) {
                mma_bf16(acc[mt][nt], aH[mt], bh);
                mma_bf16(acc[mt][nt], aL[mt], bh);
                mma_bf16(acc[mt][nt], aH[mt], bl);
            }
        }
    }
    // write gate-interleaved: [m][(j>>1)*8 + g*2 + (j&1)]
#pragma unroll
    for (int mt = 0; mt < 2; ++mt)
#pragma unroll
        for (int nt = 0; nt < 8; ++nt) {
            int r  = m0 + mt * 16 + rr;
            int cc = n0 + nt * 8 + (lane & 3) * 2;
#pragma unroll
            for (int i = 0; i < 4; ++i) {
                int m = r + (i >> 1) * 8;
                int n = cc + (i & 1);
                int dir = n >> 11, nn = n & 2047;
                int g = nn >> 9, j = nn & 511;
                d_xW[dir][m][(j >> 1) * 8 + g * 2 + (j & 1)] = acc[mt][nt][i] + d_biasC[n];
            }
        }
}

// ---------------- persistent LSTM: all 128 steps, tensor cores ---------------
// 128 CTAs (64/dir). h bf16-hi-only in fragment-major layout (1 LDG.128/kt).
// W hi+lo in smem: 2 MMAs per gate per kt. R8-style tid0-relay grid barrier.
__global__ __launch_bounds__(256)
void lstm_persist(const int* __restrict__ s1_len, const int* __restrict__ s2_len,
                  const float* __restrict__ s1_c0, const float* __restrict__ s2_c0) {
    extern __shared__ uint32_t sWf[];   // 64KB: [g(4)][kt(32)][lane(32)][bh0,bh1,bl0,bl1]
    const int tid  = threadIdx.x;
    const int lane = tid & 31;
    const int warp = tid >> 5;
    const int dir  = blockIdx.x & 1;
    const int j0   = (blockIdx.x >> 1) * 8;

    // ---- packed fragment-major weight fill (once) ----
    for (int i = tid; i < 4096; i += 256) {
        int g  = i >> 10;
        int kt = (i >> 5) & 31;
        int l  = i & 31;
        int n  = l >> 2;
        int k0 = kt * 16 + (l & 3) * 2;
        const uint32_t* srcH = (const uint32_t*)&d_Wb16[dir][0][g * Hq + j0 + n][0];
        const uint32_t* srcL = (const uint32_t*)&d_Wb16[dir][1][g * Hq + j0 + n][0];
        uint4 v;
        v.x = srcH[k0 >> 1];       v.y = srcH[(k0 + 8) >> 1];
        v.z = srcL[k0 >> 1];       v.w = srcL[(k0 + 8) >> 1];
        *(uint4*)&sWf[i * 4] = v;
    }

    // ---- per-thread ownership ----
    const int m0  = warp * 16;
    const int seq = m0 >> 6;
    const int r0  = m0 + (lane >> 2);
    const int c0j = j0 + (lane & 3) * 2;
    const int*   lens = seq ? s2_len : s1_len;
    const float* c0p  = seq ? s2_c0  : s1_c0;
    const int b0 = r0 & 63;
    const int len_[2] = { lens[b0], lens[b0 + 8] };
    const int ktW   = j0 >> 4;          // this CTA's k-tile in the h slab
    const int kslot = (j0 >> 3) & 1;

    float creg[4];
#pragma unroll
    for (int ri = 0; ri < 2; ++ri)
#pragma unroll
        for (int ci = 0; ci < 2; ++ci)
            creg[ri * 2 + ci] = c0p[(dir * Bq + b0 + 8 * ri) * Hq + c0j + ci];

    __syncthreads();

    unsigned myep = 0;

    for (int t = 0; t < Tq; ++t) {
        const int p = t & 1;
        const uint32_t* HhiF = &d_h16f[p][dir][warp][0][0][0];

        // ---- prefetch xW gate values (gate-interleaved: 2 x LDG.128 per ri) ----
        int rowx_[2];
        float4 pa[2], pb[2];
#pragma unroll
        for (int ri = 0; ri < 2; ++ri) {
            int b = b0 + 8 * ri;
            int len = len_[ri];
            int tpos = dir ? ((t < len) ? (len - 1 - t) : t) : t;
            rowx_[ri] = (seq * Bq + b) * Tq + tpos;
            const float4* x4 = (const float4*)&d_xW[dir][rowx_[ri]][(c0j >> 1) * 8];
            pa[ri] = __ldcs(x4);
            pb[ri] = __ldcs(x4 + 1);
        }

        float acc[4][4] = {};
        uint32_t aH[3][4];

#define LOADA(buf, ktv) {                                                         \
        uint4 vh = __ldcg((const uint4*)(HhiF + (ktv) * 128 + lane * 4));         \
        aH[buf][0] = vh.x; aH[buf][1] = vh.y; aH[buf][2] = vh.z; aH[buf][3] = vh.w; }

        LOADA(0, 0);
        LOADA(1, 1);

#pragma unroll
        for (int kt = 0; kt < 32; ++kt) {
            const int cur = kt % 3;
            if (kt < 30) { LOADA((kt + 2) % 3, kt + 2); }
#pragma unroll
            for (int g = 0; g < 4; ++g) {
                uint4 wv = *(const uint4*)&sWf[((g * 32 + kt) * 32 + lane) * 4];
                uint32_t bh[2] = { wv.x, wv.y };
                uint32_t bl[2] = { wv.z, wv.w };
                mma_bf16(acc[g], aH[cur], bh);   // h_hi * W_hi
                mma_bf16(acc[g], aH[cur], bl);   // h_hi * W_lo
            }
        }
#undef LOADA

        // ---- epilogue: gates, cell/h update, publish h ----
        uint32_t hhi[2];
#pragma unroll
        for (int ri = 0; ri < 2; ++ri) {
            const int rowx = rowx_[ri];
            float hv[2];
            // gate-interleaved: pa = {gi0,gi1,gf0,gf1}, pb = {gg0,gg1,go0,go1}
            {
                float gi = acc[0][ri * 2 + 0] + pa[ri].x;
                float gf = acc[1][ri * 2 + 0] + pa[ri].z;
                float gg = acc[2][ri * 2 + 0] + pb[ri].x;
                float go = acc[3][ri * 2 + 0] + pb[ri].z;
                float c  = fsigmoid(gf) * creg[ri * 2 + 0] + fsigmoid(gi) * ftanh(gg);
                hv[0]    = fsigmoid(go) * ftanh(c);
                creg[ri * 2 + 0] = c;
            }
            {
                float gi = acc[0][ri * 2 + 1] + pa[ri].y;
                float gf = acc[1][ri * 2 + 1] + pa[ri].w;
                float gg = acc[2][ri * 2 + 1] + pb[ri].y;
                float go = acc[3][ri * 2 + 1] + pb[ri].w;
                float c  = fsigmoid(gf) * creg[ri * 2 + 1] + fsigmoid(gi) * ftanh(gg);
                hv[1]    = fsigmoid(go) * ftanh(c);
                creg[ri * 2 + 1] = c;
            }
            float la, lb;
            hhi[ri] = pack_bf16(hv[0], hv[1], &la, &lb);
            *(uint32_t*)&d_Ho16[0][rowx][dir * Hq + c0j] = hhi[ri];
            *(uint32_t*)&d_Ho16[1][rowx][dir * Hq + c0j] = pack_bf16_only(la, lb);
        }
        // h state: one STG.64 (hi only)
        *(uint2*)&d_h16f[p ^ 1][dir][warp][ktW][lane][kslot * 2] = make_uint2(hhi[0], hhi[1]);

        // ---- per-direction grid barrier (R8 style: tid0 relays) ----
        __syncthreads();
        if (tid == 0) {
            __threadfence();
            unsigned arrived = atomicAdd(&g_cnt2[dir], 1);
            if (arrived == NCTA / 2 - 1) {
                g_cnt2[dir] = 0;
                __threadfence();
                atomicExch(&g_epoch2[dir], myep + 1);
            } else {
                while (*(volatile unsigned*)&g_epoch2[dir] <= myep) { }
            }
            __threadfence();
        }
        myep++;
        __syncthreads();
    }
}

// ---------------- attention projection via tensor cores ----------------------
__global__ __launch_bounds__(256)
void attn_mma() {
    const int lane = threadIdx.x & 31;
    const int warp = threadIdx.x >> 5;
    const int wm = warp & 1, wn = warp >> 1;
    const int m0 = blockIdx.y * 64 + wm * 32;
    const int n0 = wn * 64;
    const int RS = D2H / 2;
    const int kc = lane & 3;
    const int rr = lane >> 2;

    const uint32_t* Xhi = (const uint32_t*)&d_Ho16[0][0][0];
    const uint32_t* Xlo = (const uint32_t*)&d_Ho16[1][0][0];
    const uint32_t* Whi = (const uint32_t*)&d_S1W16[0][0][0];
    const uint32_t* Wlo = (const uint32_t*)&d_S1W16[1][0][0];

    float acc[2][8][4] = {};

    for (int kt = 0; kt < D2H / 16; ++kt) {
        const int k0 = kt * 8;
        uint32_t aH[2][4], aL[2][4];
#pragma unroll
        for (int mt = 0; mt < 2; ++mt) {
            int base = (m0 + mt * 16 + rr) * RS + k0 + kc;
            aH[mt][0] = Xhi[base];          aH[mt][1] = Xhi[base + 8 * RS];
            aH[mt][2] = Xhi[base + 4];      aH[mt][3] = Xhi[base + 8 * RS + 4];
            aL[mt][0] = Xlo[base];          aL[mt][1] = Xlo[base + 8 * RS];
            aL[mt][2] = Xlo[base + 4];      aL[mt][3] = Xlo[base + 8 * RS + 4];
        }
#pragma unroll
        for (int nt = 0; nt < 8; ++nt) {
            int bb = (n0 + nt * 8 + rr) * RS + k0 + kc;
            uint32_t bh[2] = { Whi[bb], Whi[bb + 4] };
            uint32_t bl[2] = { Wlo[bb], Wlo[bb + 4] };
#pragma unroll
            for (int mt = 0; mt < 2; ++mt) {
                mma_bf16(acc[mt][nt], aH[mt], bh);
                mma_bf16(acc[mt][nt], aL[mt], bh);
                mma_bf16(acc[mt][nt], aH[mt], bl);
            }
        }
    }
#pragma unroll
    for (int mt = 0; mt < 2; ++mt)
#pragma unroll
        for (int nt = 0; nt < 8; ++nt) {
            int r  = m0 + mt * 16 + rr;
            int cc = n0 + nt * 8 + (lane & 3) * 2;
#pragma unroll
            for (int i = 0; i < 4; ++i)
                d_P[r + (i >> 1) * 8][cc + (i & 1)] = acc[mt][nt][i];
        }
}

// ---------------- masked softmax attention pooling ---------------------------
__global__ __launch_bounds__(128)
void attn_pool(const int* __restrict__ s1_len, const int* __restrict__ s2_len,
               const float* __restrict__ S2W) {
    __shared__ float sS2[Cq];
    __shared__ float ssc[Tq];
    __shared__ float red[Tq];
    int sb = blockIdx.x;
    int seq = sb >> 6, b = sb & 63;
    int t = threadIdx.x;
    for (int c = t; c < Cq; c += Tq) sS2[c] = S2W[c];
    __syncthreads();

    long row = (long)sb * Tq + t;
    float s = 0.f;
    for (int c = 0; c < Cq; ++c) s += ftanh(d_P[row][c]) * sS2[c];
    int len = (seq ? s2_len : s1_len)[b];
    ssc[t] = (t < len) ? s : -1e9f;
    __syncthreads();

    red[t] = ssc[t]; __syncthreads();
    for (int o = 64; o > 0; o >>= 1) { if (t < o) red[t] = fmaxf(red[t], red[t + o]); __syncthreads(); }
    float mx = red[0]; __syncthreads();
    float ex = expf(ssc[t] - mx);
    red[t] = ex; __syncthreads();
    for (int o = 64; o > 0; o >>= 1) { if (t < o) red[t] += red[t + o]; __syncthreads(); }
    float inv = 1.f / red[0];
    __syncthreads();
    ssc[t] = ex * inv;
    __syncthreads();

    long rowbase = (long)sb * Tq;
    for (int d = t; d < D2H; d += Tq) {
        float acc = 0.f;
        for (int tt = 0; tt < Tq; ++tt) {
            long rw = rowbase + tt;
            float h = __bfloat162float(d_Ho16[0][rw][d]) + __bfloat162float(d_Ho16[1][rw][d]);
            acc += ssc[tt] * h;
        }
        d_r[seq][b][d] = acc;
    }
}

// ---------------- final MLP head + sigmoid ----------------------------------
__global__ __launch_bounds__(512)
void final_mlp(const float* __restrict__ mlpW, const float* __restrict__ mlpb,
               const float* __restrict__ outW, const float* __restrict__ outb,
               float* __restrict__ out) {
    __shared__ float merged[4 * Hq];
    __shared__ float smlp[Mq];
    __shared__ float red[16];
    int b = blockIdx.x;
    int tid = threadIdx.x;

    for (int d = tid; d < 2 * D2H; d += Mq) {
        float v;
        if (d < D2H) v = d_r[0][b][d] + d_r[1][b][d];
        else { float df = d_r[0][b][d - D2H] - d_r[1][b][d - D2H]; v = df * df; }
        merged[d] = v;
    }
    __syncthreads();

    int warp = tid >> 5, lane = tid & 31;
    for (int m = warp * 32; m < warp * 32 + 32; ++m) {
        float p = 0.f;
        for (int d = lane; d < 4 * Hq; d += 32) p += merged[d] * mlpW[(long)m * 4 * Hq + d];
        for (int o = 16; o > 0; o >>= 1) p += __shfl_down_sync(0xffffffff, p, o);
        if (lane == 0) smlp[m] = p + mlpb[m];
    }
    __syncthreads();

    float p = smlp[tid] * outW[tid];
    for (int o = 16; o > 0; o >>= 1) p += __shfl_down_sync(0xffffffff, p, o);
    if (lane == 0) red[warp] = p;
    __syncthreads();
    if (tid == 0) {
        float l = outb[0];
        for (int w = 0; w < 16; ++w) l += red[w];
        out[b] = 1.f / (1.f + expf(-l));
    }
}

// ---------------- launch ------------------------------------------------------
extern "C" void kernel_launch(void* const* d_in, const int* in_sizes, int n_in,
                              void* d_out, int out_size) {
    const int*   s1     = (const int*)d_in[0];
    const int*   s2     = (const int*)d_in[1];
    const int*   s1_len = (const int*)d_in[2];
    const int*   s2_len = (const int*)d_in[3];
    const float* s1_h0  = (const float*)d_in[4];
    const float* s1_c0  = (const float*)d_in[5];
    const float* s2_h0  = (const float*)d_in[6];
    const float* s2_c0  = (const float*)d_in[7];
    const float* emb    = (const float*)d_in[8];
    const float* Wih_f  = (const float*)d_in[9];
    const float* Whh_f  = (const float*)d_in[10];
    const float* b_f    = (const float*)d_in[11];
    const float* Wih_b  = (const float*)d_in[12];
    const float* Whh_b  = (const float*)d_in[13];
    const float* b_b    = (const float*)d_in[14];
    const float* S1W    = (const float*)d_in[15];
    const float* S2W    = (const float*)d_in[16];
    const float* mlpW   = (const float*)d_in[17];
    const float* mlpb   = (const float*)d_in[18];
    const float* outW   = (const float*)d_in[19];
    const float* outb   = (const float*)d_in[20];
    float* out = (float*)d_out;

    const int smem_lstm = 16384 * (int)sizeof(uint32_t);   // 64KB
    cudaFuncSetAttribute(lstm_persist, cudaFuncAttributeMaxDynamicSharedMemorySize, smem_lstm);

    init_state<<<(2 * 128 * (Hq / 2) + 255) / 256, 256>>>(s1_h0, s2_h0);
    prep_weights<<<(2 * G4H * Hq + 255) / 256, 256>>>(Whh_f, Whh_b);
    gather_convert<<<(NROWS * KE + 255) / 256, 256>>>(s1, s2, emb);
    convert_wih<<<(2 * G4H * KE + 255) / 256, 256>>>(Wih_f, Wih_b, b_f, b_b);
    convert_s1w<<<(Cq * D2H + 255) / 256, 256>>>(S1W);

    xw_mma<<<dim3(16, 256), 256>>>();                  // both dirs fused

    lstm_persist<<<NCTA, 256, smem_lstm>>>(s1_len, s2_len, s1_c0, s2_c0);

    attn_mma<<<dim3(1, 256), 256>>>();
    attn_pool<<<128, 128>>>(s1_len, s2_len, S2W);
    final_mlp<<<Bq, 512>>>(mlpW, mlpb, outW, outb, out);
}

// round 11
// speedup vs baseline: 1.2481x; 1.0567x over previous
#include <cuda_runtime.h>
#include <cuda_bf16.h>
#include <stdint.h>
#include <math.h>

// Problem constants
#define Bq   64
#define Tq   128
#define Eq   300
#define Hq   512
#define Cq   256
#define Mq   512
#define RPS  (Bq*Tq)      // rows per sequence: 8192
#define NROWS (2*RPS)     // 16384
#define G4H  (4*Hq)       // 2048
#define D2H  (2*Hq)       // 1024
#define NCTA 128          // persistent LSTM grid (64 per direction)
#define KE   304          // Eq padded to multiple of 16

// -------- scratch (static device globals; no allocation anywhere) -----------
// xW in gate-interleaved layout: [dir][row][(j>>1)*8 + gate*2 + (j&1)]
__device__ float d_xW[2][NROWS][G4H];
__device__ float d_P[NROWS][Cq];         // attention pre-activations
__device__ float d_r[2][Bq][D2H];        // pooled representations
__device__ __nv_bfloat16 d_Wb16[2][2][G4H][Hq];      // [dir][hi/lo][n][k]  Whh
// h state (bf16 hi only) in mma-A-fragment-major layout:
// [parity][dir][mblock(8)][ktile(32)][lane(32)][slot(4)]  (u32 = 2 bf16)
__device__ uint32_t d_h16f[2][2][8][32][32][4];
__device__ __nv_bfloat16 d_x16[2][NROWS][KE];        // [hi/lo] gathered embeddings
__device__ __nv_bfloat16 d_W16[2][2*G4H][KE];        // [hi/lo][dir*2048+n][k] Wih
__device__ float d_biasC[2*G4H];                     // combined Wih bias
__device__ __nv_bfloat16 d_Ho16[2][NROWS][D2H];      // [hi/lo] bf16 Hout (full precision)
__device__ __nv_bfloat16 d_S1W16[2][Cq][D2H];        // [hi/lo] S1W
__device__ unsigned g_cnt2[2];
__device__ unsigned g_epoch2[2];

// ---- fast activations (MUFU.EX2-based) --------------------------------------
__device__ __forceinline__ float fsigmoid(float x) {
    return __fdividef(1.f, 1.f + __expf(-x));
}
__device__ __forceinline__ float ftanh(float x) {
    return 1.f - __fdividef(2.f, 1.f + __expf(2.f * x));
}
__device__ __forceinline__ uint32_t pack_bf16(float a, float b, float* lo_a, float* lo_b) {
    __nv_bfloat16 ha = __float2bfloat16(a);
    __nv_bfloat16 hb = __float2bfloat16(b);
    *lo_a = a - __bfloat162float(ha);
    *lo_b = b - __bfloat162float(hb);
    return (uint32_t)__bfloat16_as_ushort(ha) | ((uint32_t)__bfloat16_as_ushort(hb) << 16);
}
__device__ __forceinline__ uint32_t pack_bf16_only(float a, float b) {
    return (uint32_t)__bfloat16_as_ushort(__float2bfloat16(a)) |
           ((uint32_t)__bfloat16_as_ushort(__float2bfloat16(b)) << 16);
}

// ---------------- init: reset barriers, seed h frag slab from h0 -------------
__global__ void init_state(const float* s1_h0, const float* s2_h0) {
    int idx = blockIdx.x * blockDim.x + threadIdx.x;
    if (idx < 2) { g_cnt2[idx] = 0; g_epoch2[idx] = 0; }
    if (idx >= 2 * 128 * (Hq / 2)) return;
    int jj  = idx % (Hq / 2);       // u32 pair index
    int j   = jj * 2;
    int m   = (idx / (Hq / 2)) % 128;
    int dir = idx / ((Hq / 2) * 128);
    int seq = m >> 6, b = m & 63;
    const float* h0 = seq ? s2_h0 : s1_h0;
    float h0a = h0[(dir * Bq + b) * Hq + j];
    float h0b = h0[(dir * Bq + b) * Hq + j + 1];
    uint32_t uhi = pack_bf16_only(h0a, h0b);
    int mb   = m >> 4;
    int kt   = j >> 4;
    int lane = (m & 7) * 4 + ((j >> 1) & 3);
    int slot = ((j & 15) >> 3) * 2 + ((m & 15) >> 3);
    d_h16f[0][dir][mb][kt][lane][slot] = uhi;
}

// ---------------- split Whh into bf16 hi/lo ----------------------------------
__global__ void prep_weights(const float* __restrict__ Whh_f,
                             const float* __restrict__ Whh_b) {
    int idx = blockIdx.x * blockDim.x + threadIdx.x;
    if (idx >= 2 * G4H * Hq) return;
    int dir = idx / (G4H * Hq);
    int r   = idx % (G4H * Hq);
    float w = (dir ? Whh_b : Whh_f)[r];
    __nv_bfloat16 hi = __float2bfloat16(w);
    __nv_bfloat16 lo = __float2bfloat16(w - __bfloat162float(hi));
    int n = r / Hq, k = r % Hq;
    d_Wb16[dir][0][n][k] = hi;
    d_Wb16[dir][1][n][k] = lo;
}

// ---------------- gather tokens + convert emb rows to bf16 hi/lo -------------
__global__ void gather_convert(const int* __restrict__ s1, const int* __restrict__ s2,
                               const float* __restrict__ emb) {
    int idx = blockIdx.x * blockDim.x + threadIdx.x;
    if (idx >= NROWS * KE) return;
    int m = idx / KE, k = idx % KE;
    int tok = (m < RPS) ? s1[m] : s2[m - RPS];
    float v = (k < Eq) ? emb[(long)tok * Eq + k] : 0.f;
    __nv_bfloat16 hi = __float2bfloat16(v);
    d_x16[0][m][k] = hi;
    d_x16[1][m][k] = __float2bfloat16(v - __bfloat162float(hi));
}

// ---------------- convert Wih (both dirs) to bf16 hi/lo + combined bias ------
__global__ void convert_wih(const float* __restrict__ Wih_f, const float* __restrict__ Wih_b,
                            const float* __restrict__ b_f, const float* __restrict__ b_b) {
    int idx = blockIdx.x * blockDim.x + threadIdx.x;
    if (idx >= 2 * G4H * KE) return;
    int n = idx / KE, k = idx % KE;
    int dir = n >> 11, nn = n & 2047;
    const float* W = dir ? Wih_b : Wih_f;
    float v = (k < Eq) ? W[(long)nn * Eq + k] : 0.f;
    __nv_bfloat16 hi = __float2bfloat16(v);
    d_W16[0][n][k] = hi;
    d_W16[1][n][k] = __float2bfloat16(v - __bfloat162float(hi));
    if (k == 0) d_biasC[n] = (dir ? b_b : b_f)[nn];
}

// ---------------- convert S1W to bf16 hi/lo -----------------------------------
__global__ void convert_s1w(const float* __restrict__ S1W) {
    int idx = blockIdx.x * blockDim.x + threadIdx.x;
    if (idx >= Cq * D2H) return;
    float v = S1W[idx];
    int c = idx / D2H, k = idx % D2H;
    __nv_bfloat16 hi = __float2bfloat16(v);
    d_S1W16[0][c][k] = hi;
    d_S1W16[1][c][k] = __float2bfloat16(v - __bfloat162float(hi));
}

// ---------------- mma.sync bf16 helper ---------------------------------------
__device__ __forceinline__ void mma_bf16(float* d, const uint32_t* a, const uint32_t* b) {
    asm volatile(
        "mma.sync.aligned.m16n8k16.row.col.f32.bf16.bf16.f32 "
        "{%0,%1,%2,%3}, {%4,%5,%6,%7}, {%8,%9}, {%0,%1,%2,%3};\n"
        : "+f"(d[0]), "+f"(d[1]), "+f"(d[2]), "+f"(d[3])
        : "r"(a[0]), "r"(a[1]), "r"(a[2]), "r"(a[3]),
          "r"(b[0]), "r"(b[1]));
}

// ---------------- xW via tensor cores: [16384,304] @ [304,4096] --------------
__global__ __launch_bounds__(256)
void xw_mma() {
    const int lane = threadIdx.x & 31;
    const int warp = threadIdx.x >> 5;
    const int wm = warp & 1, wn = warp >> 1;
    const int m0 = blockIdx.y * 64 + wm * 32;
    const int n0 = blockIdx.x * 256 + wn * 64;
    const int RS = KE / 2;                 // u32 row stride (152)
    const int kc = lane & 3;
    const int rr = lane >> 2;

    const uint32_t* Xhi = (const uint32_t*)&d_x16[0][0][0];
    const uint32_t* Xlo = (const uint32_t*)&d_x16[1][0][0];
    const uint32_t* Whi = (const uint32_t*)&d_W16[0][0][0];
    const uint32_t* Wlo = (const uint32_t*)&d_W16[1][0][0];

    float acc[2][8][4] = {};

    for (int kt = 0; kt < KE / 16; ++kt) {
        const int k0 = kt * 8;
        uint32_t aH[2][4], aL[2][4];
#pragma unroll
        for (int mt = 0; mt < 2; ++mt) {
            int base = (m0 + mt * 16 + rr) * RS + k0 + kc;
            aH[mt][0] = Xhi[base];          aH[mt][1] = Xhi[base + 8 * RS];
            aH[mt][2] = Xhi[base + 4];      aH[mt][3] = Xhi[base + 8 * RS + 4];
            aL[mt][0] = Xlo[base];          aL[mt][1] = Xlo[base + 8 * RS];
            aL[mt][2] = Xlo[base + 4];      aL[mt][3] = Xlo[base + 8 * RS + 4];
        }
#pragma unroll
        for (int nt = 0; nt < 8; ++nt) {
            int bb = (n0 + nt * 8 + rr) * RS + k0 + kc;
            uint32_t bh[2] = { Whi[bb], Whi[bb + 4] };
            uint32_t bl[2] = { Wlo[bb], Wlo[bb + 4] };
#pragma unroll
            for (int mt = 0; mt < 2; ++mt) {
                mma_bf16(acc[mt][nt], aH[mt], bh);
                mma_bf16(acc[mt][nt], aL[mt], bh);
                mma_bf16(acc[mt][nt], aH[mt], bl);
            }
        }
    }
    // write gate-interleaved: [m][(j>>1)*8 + g*2 + (j&1)]
#pragma unroll
    for (int mt = 0; mt < 2; ++mt)
#pragma unroll
        for (int nt = 0; nt < 8; ++nt) {
            int r  = m0 + mt * 16 + rr;
            int cc = n0 + nt * 8 + (lane & 3) * 2;
#pragma unroll
            for (int i = 0; i < 4; ++i) {
                int m = r + (i >> 1) * 8;
                int n = cc + (i & 1);
                int dir = n >> 11, nn = n & 2047;
                int g = nn >> 9, j = nn & 511;
                d_xW[dir][m][(j >> 1) * 8 + g * 2 + (j & 1)] = acc[mt][nt][i] + d_biasC[n];
            }
        }
}

// ---------------- persistent LSTM: all 128 steps, tensor cores ---------------
// 128 CTAs (64/dir). h bf16-hi-only fragment-major (1 LDG.128/kt, 5-deep ring).
// Ho16 stores + next-step xW prefetch overlapped with the barrier wait.
__global__ __launch_bounds__(256)
void lstm_persist(const int* __restrict__ s1_len, const int* __restrict__ s2_len,
                  const float* __restrict__ s1_c0, const float* __restrict__ s2_c0) {
    extern __shared__ uint32_t sWf[];   // 64KB: [g(4)][kt(32)][lane(32)][bh0,bh1,bl0,bl1]
    const int tid  = threadIdx.x;
    const int lane = tid & 31;
    const int warp = tid >> 5;
    const int dir  = blockIdx.x & 1;
    const int j0   = (blockIdx.x >> 1) * 8;

    // ---- packed fragment-major weight fill (once) ----
    for (int i = tid; i < 4096; i += 256) {
        int g  = i >> 10;
        int kt = (i >> 5) & 31;
        int l  = i & 31;
        int n  = l >> 2;
        int k0 = kt * 16 + (l & 3) * 2;
        const uint32_t* srcH = (const uint32_t*)&d_Wb16[dir][0][g * Hq + j0 + n][0];
        const uint32_t* srcL = (const uint32_t*)&d_Wb16[dir][1][g * Hq + j0 + n][0];
        uint4 v;
        v.x = srcH[k0 >> 1];       v.y = srcH[(k0 + 8) >> 1];
        v.z = srcL[k0 >> 1];       v.w = srcL[(k0 + 8) >> 1];
        *(uint4*)&sWf[i * 4] = v;
    }

    // ---- per-thread ownership ----
    const int m0  = warp * 16;
    const int seq = m0 >> 6;
    const int r0  = m0 + (lane >> 2);
    const int c0j = j0 + (lane & 3) * 2;
    const int*   lens = seq ? s2_len : s1_len;
    const float* c0p  = seq ? s2_c0  : s1_c0;
    const int b0 = r0 & 63;
    const int len_[2] = { lens[b0], lens[b0 + 8] };
    const int ktW   = j0 >> 4;          // this CTA's k-tile in the h slab
    const int kslot = (j0 >> 3) & 1;

    float creg[4];
#pragma unroll
    for (int ri = 0; ri < 2; ++ri)
#pragma unroll
        for (int ci = 0; ci < 2; ++ci)
            creg[ri * 2 + ci] = c0p[(dir * Bq + b0 + 8 * ri) * Hq + c0j + ci];

    __syncthreads();

    unsigned myep = 0;

    // ---- prefetch xW for step 0 ----
    int rowx_[2];
    float4 pa[2], pb[2];
#pragma unroll
    for (int ri = 0; ri < 2; ++ri) {
        int b = b0 + 8 * ri;
        int len = len_[ri];
        int tpos = dir ? (len - 1) : 0;           // t=0: reversed start is len-1
        rowx_[ri] = (seq * Bq + b) * Tq + tpos;
        const float4* x4 = (const float4*)&d_xW[dir][rowx_[ri]][(c0j >> 1) * 8];
        pa[ri] = __ldcs(x4);
        pb[ri] = __ldcs(x4 + 1);
    }

    for (int t = 0; t < Tq; ++t) {
        const int p = t & 1;
        const uint32_t* HhiF = &d_h16f[p][dir][warp][0][0][0];

        float acc[4][4] = {};
        uint32_t aH[5][4];

#define LOADA(buf, ktv) {                                                         \
        uint4 vh = __ldcg((const uint4*)(HhiF + (ktv) * 128 + lane * 4));         \
        aH[buf][0] = vh.x; aH[buf][1] = vh.y; aH[buf][2] = vh.z; aH[buf][3] = vh.w; }

        LOADA(0, 0); LOADA(1, 1); LOADA(2, 2); LOADA(3, 3);

#pragma unroll
        for (int kt = 0; kt < 32; ++kt) {
            const int cur = kt % 5;
            if (kt < 28) { LOADA((kt + 4) % 5, kt + 4); }
#pragma unroll
            for (int g = 0; g < 4; ++g) {
                uint4 wv = *(const uint4*)&sWf[((g * 32 + kt) * 32 + lane) * 4];
                uint32_t bh[2] = { wv.x, wv.y };
                uint32_t bl[2] = { wv.z, wv.w };
                mma_bf16(acc[g], aH[cur], bh);   // h_hi * W_hi
                mma_bf16(acc[g], aH[cur], bl);   // h_hi * W_lo
            }
        }
#undef LOADA

        // ---- epilogue: gates, cell/h update ----
        uint32_t hhi[2], hlo[2];
#pragma unroll
        for (int ri = 0; ri < 2; ++ri) {
            float hv[2];
            // gate-interleaved: pa = {gi0,gi1,gf0,gf1}, pb = {gg0,gg1,go0,go1}
            {
                float gi = acc[0][ri * 2 + 0] + pa[ri].x;
                float gf = acc[1][ri * 2 + 0] + pa[ri].z;
                float gg = acc[2][ri * 2 + 0] + pb[ri].x;
                float go = acc[3][ri * 2 + 0] + pb[ri].z;
                float c  = fsigmoid(gf) * creg[ri * 2 + 0] + fsigmoid(gi) * ftanh(gg);
                hv[0]    = fsigmoid(go) * ftanh(c);
                creg[ri * 2 + 0] = c;
            }
            {
                float gi = acc[0][ri * 2 + 1] + pa[ri].y;
                float gf = acc[1][ri * 2 + 1] + pa[ri].w;
                float gg = acc[2][ri * 2 + 1] + pb[ri].y;
                float go = acc[3][ri * 2 + 1] + pb[ri].w;
                float c  = fsigmoid(gf) * creg[ri * 2 + 1] + fsigmoid(gi) * ftanh(gg);
                hv[1]    = fsigmoid(go) * ftanh(c);
                creg[ri * 2 + 1] = c;
            }
            float la, lb;
            hhi[ri] = pack_bf16(hv[0], hv[1], &la, &lb);
            hlo[ri] = pack_bf16_only(la, lb);
        }
        // publish h-state FIRST (only data other CTAs need): one STG.64
        *(uint2*)&d_h16f[p ^ 1][dir][warp][ktW][lane][kslot * 2] = make_uint2(hhi[0], hhi[1]);

        // ---- barrier arrive ----
        __syncthreads();
        if (tid == 0) {
            __threadfence();
            unsigned arrived = atomicAdd(&g_cnt2[dir], 1);
            if (arrived == NCTA / 2 - 1) {
                g_cnt2[dir] = 0;
                __threadfence();
                atomicExch(&g_epoch2[dir], myep + 1);
            }
        }

        // ---- overlapped with barrier wait: Ho16 stores + next xW prefetch ----
#pragma unroll
        for (int ri = 0; ri < 2; ++ri) {
            *(uint32_t*)&d_Ho16[0][rowx_[ri]][dir * Hq + c0j] = hhi[ri];
            *(uint32_t*)&d_Ho16[1][rowx_[ri]][dir * Hq + c0j] = hlo[ri];
        }
        int nrowx[2];
        float4 npa[2], npb[2];
        if (t + 1 < Tq) {
            const int tn = t + 1;
#pragma unroll
            for (int ri = 0; ri < 2; ++ri) {
                int b = b0 + 8 * ri;
                int len = len_[ri];
                int tpos = dir ? ((tn < len) ? (len - 1 - tn) : tn) : tn;
                nrowx[ri] = (seq * Bq + b) * Tq + tpos;
                const float4* x4 = (const float4*)&d_xW[dir][nrowx[ri]][(c0j >> 1) * 8];
                npa[ri] = __ldcs(x4);
                npb[ri] = __ldcs(x4 + 1);
            }
        }

        // ---- barrier wait (tid0 polls; rest wait at syncthreads) ----
        if (tid == 0) {
            while (*(volatile unsigned*)&g_epoch2[dir] <= myep) { }
            __threadfence();
        }
        myep++;
        __syncthreads();

        if (t + 1 < Tq) {
#pragma unroll
            for (int ri = 0; ri < 2; ++ri) {
                rowx_[ri] = nrowx[ri];
                pa[ri] = npa[ri];
                pb[ri] = npb[ri];
            }
        }
    }
}

// ---------------- attention projection via tensor cores ----------------------
__global__ __launch_bounds__(256)
void attn_mma() {
    const int lane = threadIdx.x & 31;
    const int warp = threadIdx.x >> 5;
    const int wm = warp & 1, wn = warp >> 1;
    const int m0 = blockIdx.y * 64 + wm * 32;
    const int n0 = wn * 64;
    const int RS = D2H / 2;
    const int kc = lane & 3;
    const int rr = lane >> 2;

    const uint32_t* Xhi = (const uint32_t*)&d_Ho16[0][0][0];
    const uint32_t* Xlo = (const uint32_t*)&d_Ho16[1][0][0];
    const uint32_t* Whi = (const uint32_t*)&d_S1W16[0][0][0];
    const uint32_t* Wlo = (const uint32_t*)&d_S1W16[1][0][0];

    float acc[2][8][4] = {};

    for (int kt = 0; kt < D2H / 16; ++kt) {
        const int k0 = kt * 8;
        uint32_t aH[2][4], aL[2][4];
#pragma unroll
        for (int mt = 0; mt < 2; ++mt) {
            int base = (m0 + mt * 16 + rr) * RS + k0 + kc;
            aH[mt][0] = Xhi[base];          aH[mt][1] = Xhi[base + 8 * RS];
            aH[mt][2] = Xhi[base + 4];      aH[mt][3] = Xhi[base + 8 * RS + 4];
            aL[mt][0] = Xlo[base];          aL[mt][1] = Xlo[base + 8 * RS];
            aL[mt][2] = Xlo[base + 4];      aL[mt][3] = Xlo[base + 8 * RS + 4];
        }
#pragma unroll
        for (int nt = 0; nt < 8; ++nt) {
            int bb = (n0 + nt * 8 + rr) * RS + k0 + kc;
            uint32_t bh[2] = { Whi[bb], Whi[bb + 4] };
            uint32_t bl[2] = { Wlo[bb], Wlo[bb + 4] };
#pragma unroll
            for (int mt = 0; mt < 2; ++mt) {
                mma_bf16(acc[mt][nt], aH[mt], bh);
                mma_bf16(acc[mt][nt], aL[mt], bh);
                mma_bf16(acc[mt][nt], aH[mt], bl);
            }
        }
    }
#pragma unroll
    for (int mt = 0; mt < 2; ++mt)
#pragma unroll
        for (int nt = 0; nt < 8; ++nt) {
            int r  = m0 + mt * 16 + rr;
            int cc = n0 + nt * 8 + (lane & 3) * 2;
#pragma unroll
            for (int i = 0; i < 4; ++i)
                d_P[r + (i >> 1) * 8][cc + (i & 1)] = acc[mt][nt][i];
        }
}

// ---------------- masked softmax attention pooling ---------------------------
__global__ __launch_bounds__(128)
void attn_pool(const int* __restrict__ s1_len, const int* __restrict__ s2_len,
               const float* __restrict__ S2W) {
    __shared__ float sS2[Cq];
    __shared__ float ssc[Tq];
    __shared__ float red[Tq];
    int sb = blockIdx.x;
    int seq = sb >> 6, b = sb & 63;
    int t = threadIdx.x;
    for (int c = t; c < Cq; c += Tq) sS2[c] = S2W[c];
    __syncthreads();

    long row = (long)sb * Tq + t;
    float s = 0.f;
    for (int c = 0; c < Cq; ++c) s += ftanh(d_P[row][c]) * sS2[c];
    int len = (seq ? s2_len : s1_len)[b];
    ssc[t] = (t < len) ? s : -1e9f;
    __syncthreads();

    red[t] = ssc[t]; __syncthreads();
    for (int o = 64; o > 0; o >>= 1) { if (t < o) red[t] = fmaxf(red[t], red[t + o]); __syncthreads(); }
    float mx = red[0]; __syncthreads();
    float ex = expf(ssc[t] - mx);
    red[t] = ex; __syncthreads();
    for (int o = 64; o > 0; o >>= 1) { if (t < o) red[t] += red[t + o]; __syncthreads(); }
    float inv = 1.f / red[0];
    __syncthreads();
    ssc[t] = ex * inv;
    __syncthreads();

    long rowbase = (long)sb * Tq;
    for (int d2 = t; d2 < D2H / 2; d2 += Tq) {   // packed bf16x2 pooling
        float acc0 = 0.f, acc1 = 0.f;
        for (int tt = 0; tt < Tq; ++tt) {
            long rw = rowbase + tt;
            __nv_bfloat162 h2 = *(const __nv_bfloat162*)&d_Ho16[0][rw][d2 * 2];
            __nv_bfloat162 l2 = *(const __nv_bfloat162*)&d_Ho16[1][rw][d2 * 2];
            float w = ssc[tt];
            acc0 += w * (__bfloat162float(h2.x) + __bfloat162float(l2.x));
            acc1 += w * (__bfloat162float(h2.y) + __bfloat162float(l2.y));
        }
        d_r[seq][b][d2 * 2]     = acc0;
        d_r[seq][b][d2 * 2 + 1] = acc1;
    }
}

// ---------------- final MLP head + sigmoid ----------------------------------
__global__ __launch_bounds__(512)
void final_mlp(const float* __restrict__ mlpW, const float* __restrict__ mlpb,
               const float* __restrict__ outW, const float* __restrict__ outb,
               float* __restrict__ out) {
    __shared__ float merged[4 * Hq];
    __shared__ float smlp[Mq];
    __shared__ float red[16];
    int b = blockIdx.x;
    int tid = threadIdx.x;

    for (int d = tid; d < 2 * D2H; d += Mq) {
        float v;
        if (d < D2H) v = d_r[0][b][d] + d_r[1][b][d];
        else { float df = d_r[0][b][d - D2H] - d_r[1][b][d - D2H]; v = df * df; }
        merged[d] = v;
    }
    __syncthreads();

    int warp = tid >> 5, lane = tid & 31;
    for (int m = warp * 32; m < warp * 32 + 32; ++m) {
        float p = 0.f;
        for (int d = lane; d < 4 * Hq; d += 32) p += merged[d] * mlpW[(long)m * 4 * Hq + d];
        for (int o = 16; o > 0; o >>= 1) p += __shfl_down_sync(0xffffffff, p, o);
        if (lane == 0) smlp[m] = p + mlpb[m];
    }
    __syncthreads();

    float p = smlp[tid] * outW[tid];
    for (int o = 16; o > 0; o >>= 1) p += __shfl_down_sync(0xffffffff, p, o);
    if (lane == 0) red[warp] = p;
    __syncthreads();
    if (tid == 0) {
        float l = outb[0];
        for (int w = 0; w < 16; ++w) l += red[w];
        out[b] = 1.f / (1.f + expf(-l));
    }
}

// ---------------- launch ------------------------------------------------------
extern "C" void kernel_launch(void* const* d_in, const int* in_sizes, int n_in,
                              void* d_out, int out_size) {
    const int*   s1     = (const int*)d_in[0];
    const int*   s2     = (const int*)d_in[1];
    const int*   s1_len = (const int*)d_in[2];
    const int*   s2_len = (const int*)d_in[3];
    const float* s1_h0  = (const float*)d_in[4];
    const float* s1_c0  = (const float*)d_in[5];
    const float* s2_h0  = (const float*)d_in[6];
    const float* s2_c0  = (const float*)d_in[7];
    const float* emb    = (const float*)d_in[8];
    const float* Wih_f  = (const float*)d_in[9];
    const float* Whh_f  = (const float*)d_in[10];
    const float* b_f    = (const float*)d_in[11];
    const float* Wih_b  = (const float*)d_in[12];
    const float* Whh_b  = (const float*)d_in[13];
    const float* b_b    = (const float*)d_in[14];
    const float* S1W    = (const float*)d_in[15];
    const float* S2W    = (const float*)d_in[16];
    const float* mlpW   = (const float*)d_in[17];
    const float* mlpb   = (const float*)d_in[18];
    const float* outW   = (const float*)d_in[19];
    const float* outb   = (const float*)d_in[20];
    float* out = (float*)d_out;

    const int smem_lstm = 16384 * (int)sizeof(uint32_t);   // 64KB
    cudaFuncSetAttribute(lstm_persist, cudaFuncAttributeMaxDynamicSharedMemorySize, smem_lstm);

    init_state<<<(2 * 128 * (Hq / 2) + 255) / 256, 256>>>(s1_h0, s2_h0);
    prep_weights<<<(2 * G4H * Hq + 255) / 256, 256>>>(Whh_f, Whh_b);
    gather_convert<<<(NROWS * KE + 255) / 256, 256>>>(s1, s2, emb);
    convert_wih<<<(2 * G4H * KE + 255) / 256, 256>>>(Wih_f, Wih_b, b_f, b_b);
    convert_s1w<<<(Cq * D2H + 255) / 256, 256>>>(S1W);

    xw_mma<<<dim3(16, 256), 256>>>();                  // both dirs fused

    lstm_persist<<<NCTA, 256, smem_lstm>>>(s1_len, s2_len, s1_c0, s2_c0);

    attn_mma<<<dim3(1, 256), 256>>>();
    attn_pool<<<128, 128>>>(s1_len, s2_len, S2W);
    final_mlp<<<Bq, 512>>>(mlpW, mlpb, outW, outb, out);
}

// round 13
// speedup vs baseline: 1.6123x; 1.2918x over previous
#include <cuda_runtime.h>
#include <cuda_bf16.h>
#include <cuda_fp16.h>
#include <stdint.h>
#include <math.h>

// Problem constants
#define Bq   64
#define Tq   128
#define Eq   300
#define Hq   512
#define Cq   256
#define Mq   512
#define RPS  (Bq*Tq)      // 8192
#define NROWS (2*RPS)     // 16384
#define G4H  (4*Hq)       // 2048
#define D2H  (2*Hq)       // 1024
#define NCTA 128          // 64 per direction
#define KE   304

// -------- scratch ------------------------------------------------------------
__device__ float d_xW[2][NROWS][G4H];    // gate-interleaved [(j>>1)*8 + g*2 + (j&1)]
__device__ float d_P[NROWS][Cq];
__device__ float d_r[2][Bq][D2H];
__device__ __half d_Wh16[2][G4H][Hq];                // fp16 Whh
// h state (fp16) in mma-A-fragment-major layout:
// [parity][dir][mblock(8)][ktile(32)][lane(32)][slot(4)]  (u32 = half2)
__device__ uint32_t d_h16f[2][2][8][32][32][4];
__device__ __half d_xh16[NROWS][KE];                 // fp16 gathered embeddings
__device__ __half d_Wih16[2*G4H][KE];                // fp16 Wih (both dirs)
__device__ float d_biasC[2*G4H];
__device__ __nv_bfloat16 d_Ho16[2][NROWS][D2H];      // bf16 hi/lo Hout (attn path)
__device__ __nv_bfloat16 d_S1W16[2][Cq][D2H];
__device__ unsigned g_cnt2[2];
__device__ unsigned g_epoch2[2];

// ---- helpers -----------------------------------------------------------------
__device__ __forceinline__ float fsigmoid(float x) { return __fdividef(1.f, 1.f + __expf(-x)); }
__device__ __forceinline__ float ftanh(float x)    { return 1.f - __fdividef(2.f, 1.f + __expf(2.f * x)); }
__device__ __forceinline__ uint32_t pack2h(float a, float b) {
    __half2 h = __floats2half2_rn(a, b);
    return *(uint32_t*)&h;
}
__device__ __forceinline__ uint32_t pack2bf(float a, float b) {
    return (uint32_t)__bfloat16_as_ushort(__float2bfloat16(a)) |
           ((uint32_t)__bfloat16_as_ushort(__float2bfloat16(b)) << 16);
}

// ---------------- init: barriers + h0 (fp16) into frag slab -------------------
__global__ void init_state(const float* s1_h0, const float* s2_h0) {
    int idx = blockIdx.x * blockDim.x + threadIdx.x;
    if (idx < 2) { g_cnt2[idx] = 0; g_epoch2[idx] = 0; }
    if (idx >= 2 * 128 * (Hq / 2)) return;
    int jj  = idx % (Hq / 2);
    int j   = jj * 2;
    int m   = (idx / (Hq / 2)) % 128;
    int dir = idx / ((Hq / 2) * 128);
    int seq = m >> 6, b = m & 63;
    const float* h0 = seq ? s2_h0 : s1_h0;
    uint32_t v = pack2h(h0[(dir * Bq + b) * Hq + j], h0[(dir * Bq + b) * Hq + j + 1]);
    int mb   = m >> 4;
    int kt   = j >> 4;
    int lane = (m & 7) * 4 + ((j >> 1) & 3);
    int slot = ((j & 15) >> 3) * 2 + ((m & 15) >> 3);
    d_h16f[0][dir][mb][kt][lane][slot] = v;
}

// ---------------- Whh -> fp16 --------------------------------------------------
__global__ void prep_weights(const float* __restrict__ Whh_f,
                             const float* __restrict__ Whh_b) {
    int idx = blockIdx.x * blockDim.x + threadIdx.x;
    if (idx >= 2 * G4H * Hq) return;
    int dir = idx / (G4H * Hq);
    int r   = idx % (G4H * Hq);
    d_Wh16[dir][r / Hq][r % Hq] = __float2half((dir ? Whh_b : Whh_f)[r]);
}

// ---------------- gather tokens + emb -> fp16 ----------------------------------
__global__ void gather_convert(const int* __restrict__ s1, const int* __restrict__ s2,
                               const float* __restrict__ emb) {
    int idx = blockIdx.x * blockDim.x + threadIdx.x;
    if (idx >= NROWS * KE) return;
    int m = idx / KE, k = idx % KE;
    int tok = (m < RPS) ? s1[m] : s2[m - RPS];
    d_xh16[m][k] = __float2half((k < Eq) ? emb[(long)tok * Eq + k] : 0.f);
}

// ---------------- Wih (both dirs) -> fp16 + combined bias ----------------------
__global__ void convert_wih(const float* __restrict__ Wih_f, const float* __restrict__ Wih_b,
                            const float* __restrict__ b_f, const float* __restrict__ b_b) {
    int idx = blockIdx.x * blockDim.x + threadIdx.x;
    if (idx >= 2 * G4H * KE) return;
    int n = idx / KE, k = idx % KE;
    int dir = n >> 11, nn = n & 2047;
    const float* W = dir ? Wih_b : Wih_f;
    d_Wih16[n][k] = __float2half((k < Eq) ? W[(long)nn * Eq + k] : 0.f);
    if (k == 0) d_biasC[n] = (dir ? b_b : b_f)[nn];
}

// ---------------- S1W -> bf16 hi/lo (attn path unchanged) ----------------------
__global__ void convert_s1w(const float* __restrict__ S1W) {
    int idx = blockIdx.x * blockDim.x + threadIdx.x;
    if (idx >= Cq * D2H) return;
    float v = S1W[idx];
    int c = idx / D2H, k = idx % D2H;
    __nv_bfloat16 hi = __float2bfloat16(v);
    d_S1W16[0][c][k] = hi;
    d_S1W16[1][c][k] = __float2bfloat16(v - __bfloat162float(hi));
}

// ---------------- mma.sync helpers ---------------------------------------------
__device__ __forceinline__ void mma_f16(float* d, const uint32_t* a, const uint32_t* b) {
    asm volatile(
        "mma.sync.aligned.m16n8k16.row.col.f32.f16.f16.f32 "
        "{%0,%1,%2,%3}, {%4,%5,%6,%7}, {%8,%9}, {%0,%1,%2,%3};\n"
        : "+f"(d[0]), "+f"(d[1]), "+f"(d[2]), "+f"(d[3])
        : "r"(a[0]), "r"(a[1]), "r"(a[2]), "r"(a[3]),
          "r"(b[0]), "r"(b[1]));
}
__device__ __forceinline__ void mma_bf16(float* d, const uint32_t* a, const uint32_t* b) {
    asm volatile(
        "mma.sync.aligned.m16n8k16.row.col.f32.bf16.bf16.f32 "
        "{%0,%1,%2,%3}, {%4,%5,%6,%7}, {%8,%9}, {%0,%1,%2,%3};\n"
        : "+f"(d[0]), "+f"(d[1]), "+f"(d[2]), "+f"(d[3])
        : "r"(a[0]), "r"(a[1]), "r"(a[2]), "r"(a[3]),
          "r"(b[0]), "r"(b[1]));
}

// ---------------- xW via fp16 tensor cores: 1 MMA per tile ---------------------
__global__ __launch_bounds__(256)
void xw_mma() {
    const int lane = threadIdx.x & 31;
    const int warp = threadIdx.x >> 5;
    const int wm = warp & 1, wn = warp >> 1;
    const int m0 = blockIdx.y * 64 + wm * 32;
    const int n0 = blockIdx.x * 256 + wn * 64;
    const int RS = KE / 2;                 // u32 row stride (152)
    const int kc = lane & 3;
    const int rr = lane >> 2;

    const uint32_t* X = (const uint32_t*)&d_xh16[0][0];
    const uint32_t* W = (const uint32_t*)&d_Wih16[0][0];

    float acc[2][8][4] = {};

    for (int kt = 0; kt < KE / 16; ++kt) {
        const int k0 = kt * 8;
        uint32_t aF[2][4];
#pragma unroll
        for (int mt = 0; mt < 2; ++mt) {
            int base = (m0 + mt * 16 + rr) * RS + k0 + kc;
            aF[mt][0] = X[base];          aF[mt][1] = X[base + 8 * RS];
            aF[mt][2] = X[base + 4];      aF[mt][3] = X[base + 8 * RS + 4];
        }
#pragma unroll
        for (int nt = 0; nt < 8; ++nt) {
            int bb = (n0 + nt * 8 + rr) * RS + k0 + kc;
            uint32_t bF[2] = { W[bb], W[bb + 4] };
#pragma unroll
            for (int mt = 0; mt < 2; ++mt)
                mma_f16(acc[mt][nt], aF[mt], bF);
        }
    }
    // write gate-interleaved: [m][(j>>1)*8 + g*2 + (j&1)]
#pragma unroll
    for (int mt = 0; mt < 2; ++mt)
#pragma unroll
        for (int nt = 0; nt < 8; ++nt) {
            int r  = m0 + mt * 16 + rr;
            int cc = n0 + nt * 8 + (lane & 3) * 2;
#pragma unroll
            for (int i = 0; i < 4; ++i) {
                int m = r + (i >> 1) * 8;
                int n = cc + (i & 1);
                int dir = n >> 11, nn = n & 2047;
                int g = nn >> 9, j = nn & 511;
                d_xW[dir][m][(j >> 1) * 8 + g * 2 + (j & 1)] = acc[mt][nt][i] + d_biasC[n];
            }
        }
}

// ---------------- persistent LSTM: fp16 single-MMA recurrence ------------------
// 128 CTAs (64/dir). h fp16 fragment-major (1 LDG.128/kt, 5-deep ring).
// W fp16 in smem [g][kt][lane][2xu32]: 1 MMA per gate per kt.
__global__ __launch_bounds__(256)
void lstm_persist(const int* __restrict__ s1_len, const int* __restrict__ s2_len,
                  const float* __restrict__ s1_c0, const float* __restrict__ s2_c0) {
    extern __shared__ uint32_t sWf[];   // 32KB: [g(4)][kt(32)][lane(32)][b0,b1]
    const int tid  = threadIdx.x;
    const int lane = tid & 31;
    const int warp = tid >> 5;
    const int dir  = blockIdx.x & 1;
    const int j0   = (blockIdx.x >> 1) * 8;

    // ---- fragment-major fp16 weight fill (once) ----
    for (int i = tid; i < 4096; i += 256) {
        int g  = i >> 10;
        int kt = (i >> 5) & 31;
        int l  = i & 31;
        int n  = l >> 2;
        int k0 = kt * 16 + (l & 3) * 2;
        const uint32_t* src = (const uint32_t*)&d_Wh16[dir][g * Hq + j0 + n][0];
        uint2 v;
        v.x = src[k0 >> 1];
        v.y = src[(k0 + 8) >> 1];
        *(uint2*)&sWf[i * 2] = v;
    }

    // ---- per-thread ownership ----
    const int m0  = warp * 16;
    const int seq = m0 >> 6;
    const int r0  = m0 + (lane >> 2);
    const int c0j = j0 + (lane & 3) * 2;
    const int*   lens = seq ? s2_len : s1_len;
    const float* c0p  = seq ? s2_c0  : s1_c0;
    const int b0 = r0 & 63;
    const int len_[2] = { lens[b0], lens[b0 + 8] };
    const int ktW   = j0 >> 4;
    const int kslot = (j0 >> 3) & 1;

    float creg[4];
#pragma unroll
    for (int ri = 0; ri < 2; ++ri)
#pragma unroll
        for (int ci = 0; ci < 2; ++ci)
            creg[ri * 2 + ci] = c0p[(dir * Bq + b0 + 8 * ri) * Hq + c0j + ci];

    __syncthreads();

    unsigned myep = 0;

    // ---- prefetch xW for step 0 ----
    int rowx_[2];
    float4 pa[2], pb[2];
#pragma unroll
    for (int ri = 0; ri < 2; ++ri) {
        int b = b0 + 8 * ri;
        int len = len_[ri];
        int tpos = dir ? (len - 1) : 0;
        rowx_[ri] = (seq * Bq + b) * Tq + tpos;
        const float4* x4 = (const float4*)&d_xW[dir][rowx_[ri]][(c0j >> 1) * 8];
        pa[ri] = __ldcs(x4);
        pb[ri] = __ldcs(x4 + 1);
    }

    for (int t = 0; t < Tq; ++t) {
        const int p = t & 1;
        const uint32_t* HF = &d_h16f[p][dir][warp][0][0][0];

        float acc[4][4] = {};
        uint32_t aF[5][4];

#define LOADA(buf, ktv) {                                                         \
        uint4 vh = __ldcg((const uint4*)(HF + (ktv) * 128 + lane * 4));           \
        aF[buf][0] = vh.x; aF[buf][1] = vh.y; aF[buf][2] = vh.z; aF[buf][3] = vh.w; }

        LOADA(0, 0); LOADA(1, 1); LOADA(2, 2); LOADA(3, 3);

#pragma unroll
        for (int kt = 0; kt < 32; ++kt) {
            const int cur = kt % 5;
            if (kt < 28) { LOADA((kt + 4) % 5, kt + 4); }
#pragma unroll
            for (int g = 0; g < 4; ++g) {
                uint2 wv = *(const uint2*)&sWf[((g * 32 + kt) * 32 + lane) * 2];
                uint32_t bF[2] = { wv.x, wv.y };
                mma_f16(acc[g], aF[cur], bF);
            }
        }
#undef LOADA

        // ---- epilogue: gates, cell/h update ----
        uint32_t hh[2];
        float hv_[2][2];
#pragma unroll
        for (int ri = 0; ri < 2; ++ri) {
            float hv[2];
            {
                float gi = acc[0][ri * 2 + 0] + pa[ri].x;
                float gf = acc[1][ri * 2 + 0] + pa[ri].z;
                float gg = acc[2][ri * 2 + 0] + pb[ri].x;
                float go = acc[3][ri * 2 + 0] + pb[ri].z;
                float c  = fsigmoid(gf) * creg[ri * 2 + 0] + fsigmoid(gi) * ftanh(gg);
                hv[0]    = fsigmoid(go) * ftanh(c);
                creg[ri * 2 + 0] = c;
            }
            {
                float gi = acc[0][ri * 2 + 1] + pa[ri].y;
                float gf = acc[1][ri * 2 + 1] + pa[ri].w;
                float gg = acc[2][ri * 2 + 1] + pb[ri].y;
                float go = acc[3][ri * 2 + 1] + pb[ri].w;
                float c  = fsigmoid(gf) * creg[ri * 2 + 1] + fsigmoid(gi) * ftanh(gg);
                hv[1]    = fsigmoid(go) * ftanh(c);
                creg[ri * 2 + 1] = c;
            }
            hh[ri] = pack2h(hv[0], hv[1]);
            hv_[ri][0] = hv[0]; hv_[ri][1] = hv[1];
        }
        // publish h state (fp16) FIRST: one STG.64
        *(uint2*)&d_h16f[p ^ 1][dir][warp][ktW][lane][kslot * 2] = make_uint2(hh[0], hh[1]);

        // ---- barrier arrive ----
        __syncthreads();
        if (tid == 0) {
            __threadfence();
            unsigned arrived = atomicAdd(&g_cnt2[dir], 1);
            if (arrived == NCTA / 2 - 1) {
                g_cnt2[dir] = 0;
                __threadfence();
                atomicExch(&g_epoch2[dir], myep + 1);
            }
        }

        // ---- overlapped with barrier wait: Ho16 (bf16 hi/lo) + next xW prefetch ----
#pragma unroll
        for (int ri = 0; ri < 2; ++ri) {
            float a = hv_[ri][0], b2 = hv_[ri][1];
            uint32_t uhi = pack2bf(a, b2);
            uint32_t ulo = pack2bf(a - __bfloat162float(__float2bfloat16(a)),
                                   b2 - __bfloat162float(__float2bfloat16(b2)));
            *(uint32_t*)&d_Ho16[0][rowx_[ri]][dir * Hq + c0j] = uhi;
            *(uint32_t*)&d_Ho16[1][rowx_[ri]][dir * Hq + c0j] = ulo;
        }
        int nrowx[2];
        float4 npa[2], npb[2];
        if (t + 1 < Tq) {
            const int tn = t + 1;
#pragma unroll
            for (int ri = 0; ri < 2; ++ri) {
                int b = b0 + 8 * ri;
                int len = len_[ri];
                int tpos = dir ? ((tn < len) ? (len - 1 - tn) : tn) : tn;
                nrowx[ri] = (seq * Bq + b) * Tq + tpos;
                const float4* x4 = (const float4*)&d_xW[dir][nrowx[ri]][(c0j >> 1) * 8];
                npa[ri] = __ldcs(x4);
                npb[ri] = __ldcs(x4 + 1);
            }
        }

        // ---- barrier wait ----
        if (tid == 0) {
            while (*(volatile unsigned*)&g_epoch2[dir] <= myep) { }
            __threadfence();
        }
        myep++;
        __syncthreads();

        if (t + 1 < Tq) {
#pragma unroll
            for (int ri = 0; ri < 2; ++ri) {
                rowx_[ri] = nrowx[ri];
                pa[ri] = npa[ri];
                pb[ri] = npb[ri];
            }
        }
    }
}

// ---------------- attention projection (bf16 3-term, unchanged) ----------------
__global__ __launch_bounds__(256)
void attn_mma() {
    const int lane = threadIdx.x & 31;
    const int warp = threadIdx.x >> 5;
    const int wm = warp & 1, wn = warp >> 1;
    const int m0 = blockIdx.y * 64 + wm * 32;
    const int n0 = wn * 64;
    const int RS = D2H / 2;
    const int kc = lane & 3;
    const int rr = lane >> 2;

    const uint32_t* Xhi = (const uint32_t*)&d_Ho16[0][0][0];
    const uint32_t* Xlo = (const uint32_t*)&d_Ho16[1][0][0];
    const uint32_t* Whi = (const uint32_t*)&d_S1W16[0][0][0];
    const uint32_t* Wlo = (const uint32_t*)&d_S1W16[1][0][0];

    float acc[2][8][4] = {};

    for (int kt = 0; kt < D2H / 16; ++kt) {
        const int k0 = kt * 8;
        uint32_t aH[2][4], aL[2][4];
#pragma unroll
        for (int mt = 0; mt < 2; ++mt) {
            int base = (m0 + mt * 16 + rr) * RS + k0 + kc;
            aH[mt][0] = Xhi[base];          aH[mt][1] = Xhi[base + 8 * RS];
            aH[mt][2] = Xhi[base + 4];      aH[mt][3] = Xhi[base + 8 * RS + 4];
            aL[mt][0] = Xlo[base];          aL[mt][1] = Xlo[base + 8 * RS];
            aL[mt][2] = Xlo[base + 4];      aL[mt][3] = Xlo[base + 8 * RS + 4];
        }
#pragma unroll
        for (int nt = 0; nt < 8; ++nt) {
            int bb = (n0 + nt * 8 + rr) * RS + k0 + kc;
            uint32_t bh[2] = { Whi[bb], Whi[bb + 4] };
            uint32_t bl[2] = { Wlo[bb], Wlo[bb + 4] };
#pragma unroll
            for (int mt = 0; mt < 2; ++mt) {
                mma_bf16(acc[mt][nt], aH[mt], bh);
                mma_bf16(acc[mt][nt], aL[mt], bh);
                mma_bf16(acc[mt][nt], aH[mt], bl);
            }
        }
    }
#pragma unroll
    for (int mt = 0; mt < 2; ++mt)
#pragma unroll
        for (int nt = 0; nt < 8; ++nt) {
            int r  = m0 + mt * 16 + rr;
            int cc = n0 + nt * 8 + (lane & 3) * 2;
#pragma unroll
            for (int i = 0; i < 4; ++i)
                d_P[r + (i >> 1) * 8][cc + (i & 1)] = acc[mt][nt][i];
        }
}

// ---------------- masked softmax attention pooling ------------------------------
__global__ __launch_bounds__(128)
void attn_pool(const int* __restrict__ s1_len, const int* __restrict__ s2_len,
               const float* __restrict__ S2W) {
    __shared__ float sS2[Cq];
    __shared__ float ssc[Tq];
    __shared__ float red[Tq];
    int sb = blockIdx.x;
    int seq = sb >> 6, b = sb & 63;
    int t = threadIdx.x;
    for (int c = t; c < Cq; c += Tq) sS2[c] = S2W[c];
    __syncthreads();

    long row = (long)sb * Tq + t;
    float s = 0.f;
    for (int c = 0; c < Cq; ++c) s += ftanh(d_P[row][c]) * sS2[c];
    int len = (seq ? s2_len : s1_len)[b];
    ssc[t] = (t < len) ? s : -1e9f;
    __syncthreads();

    red[t] = ssc[t]; __syncthreads();
    for (int o = 64; o > 0; o >>= 1) { if (t < o) red[t] = fmaxf(red[t], red[t + o]); __syncthreads(); }
    float mx = red[0]; __syncthreads();
    float ex = expf(ssc[t] - mx);
    red[t] = ex; __syncthreads();
    for (int o = 64; o > 0; o >>= 1) { if (t < o) red[t] += red[t + o]; __syncthreads(); }
    float inv = 1.f / red[0];
    __syncthreads();
    ssc[t] = ex * inv;
    __syncthreads();

    long rowbase = (long)sb * Tq;
    for (int d2 = t; d2 < D2H / 2; d2 += Tq) {
        float acc0 = 0.f, acc1 = 0.f;
        for (int tt = 0; tt < Tq; ++tt) {
            long rw = rowbase + tt;
            __nv_bfloat162 h2 = *(const __nv_bfloat162*)&d_Ho16[0][rw][d2 * 2];
            __nv_bfloat162 l2 = *(const __nv_bfloat162*)&d_Ho16[1][rw][d2 * 2];
            float w = ssc[tt];
            acc0 += w * (__bfloat162float(h2.x) + __bfloat162float(l2.x));
            acc1 += w * (__bfloat162float(h2.y) + __bfloat162float(l2.y));
        }
        d_r[seq][b][d2 * 2]     = acc0;
        d_r[seq][b][d2 * 2 + 1] = acc1;
    }
}

// ---------------- final MLP head + sigmoid --------------------------------------
__global__ __launch_bounds__(512)
void final_mlp(const float* __restrict__ mlpW, const float* __restrict__ mlpb,
               const float* __restrict__ outW, const float* __restrict__ outb,
               float* __restrict__ out) {
    __shared__ float merged[4 * Hq];
    __shared__ float smlp[Mq];
    __shared__ float red[16];
    int b = blockIdx.x;
    int tid = threadIdx.x;

    for (int d = tid; d < 2 * D2H; d += Mq) {
        float v;
        if (d < D2H) v = d_r[0][b][d] + d_r[1][b][d];
        else { float df = d_r[0][b][d - D2H] - d_r[1][b][d - D2H]; v = df * df; }
        merged[d] = v;
    }
    __syncthreads();

    int warp = tid >> 5, lane = tid & 31;
    for (int m = warp * 32; m < warp * 32 + 32; ++m) {
        float p = 0.f;
        for (int d = lane; d < 4 * Hq; d += 32) p += merged[d] * mlpW[(long)m * 4 * Hq + d];
        for (int o = 16; o > 0; o >>= 1) p += __shfl_down_sync(0xffffffff, p, o);
        if (lane == 0) smlp[m] = p + mlpb[m];
    }
    __syncthreads();

    float p = smlp[tid] * outW[tid];
    for (int o = 16; o > 0; o >>= 1) p += __shfl_down_sync(0xffffffff, p, o);
    if (lane == 0) red[warp] = p;
    __syncthreads();
    if (tid == 0) {
        float l = outb[0];
        for (int w = 0; w < 16; ++w) l += red[w];
        out[b] = 1.f / (1.f + expf(-l));
    }
}

// ---------------- launch ----------------------------------------------------------
extern "C" void kernel_launch(void* const* d_in, const int* in_sizes, int n_in,
                              void* d_out, int out_size) {
    const int*   s1     = (const int*)d_in[0];
    const int*   s2     = (const int*)d_in[1];
    const int*   s1_len = (const int*)d_in[2];
    const int*   s2_len = (const int*)d_in[3];
    const float* s1_h0  = (const float*)d_in[4];
    const float* s1_c0  = (const float*)d_in[5];
    const float* s2_h0  = (const float*)d_in[6];
    const float* s2_c0  = (const float*)d_in[7];
    const float* emb    = (const float*)d_in[8];
    const float* Wih_f  = (const float*)d_in[9];
    const float* Whh_f  = (const float*)d_in[10];
    const float* b_f    = (const float*)d_in[11];
    const float* Wih_b  = (const float*)d_in[12];
    const float* Whh_b  = (const float*)d_in[13];
    const float* b_b    = (const float*)d_in[14];
    const float* S1W    = (const float*)d_in[15];
    const float* S2W    = (const float*)d_in[16];
    const float* mlpW   = (const float*)d_in[17];
    const float* mlpb   = (const float*)d_in[18];
    const float* outW   = (const float*)d_in[19];
    const float* outb   = (const float*)d_in[20];
    float* out = (float*)d_out;

    const int smem_lstm = 8192 * (int)sizeof(uint32_t);   // 32KB
    cudaFuncSetAttribute(lstm_persist, cudaFuncAttributeMaxDynamicSharedMemorySize, smem_lstm);

    init_state<<<(2 * 128 * (Hq / 2) + 255) / 256, 256>>>(s1_h0, s2_h0);
    prep_weights<<<(2 * G4H * Hq + 255) / 256, 256>>>(Whh_f, Whh_b);
    gather_convert<<<(NROWS * KE + 255) / 256, 256>>>(s1, s2, emb);
    convert_wih<<<(2 * G4H * KE + 255) / 256, 256>>>(Wih_f, Wih_b, b_f, b_b);
    convert_s1w<<<(Cq * D2H + 255) / 256, 256>>>(S1W);

    xw_mma<<<dim3(16, 256), 256>>>();

    lstm_persist<<<NCTA, 256, smem_lstm>>>(s1_len, s2_len, s1_c0, s2_c0);

    attn_mma<<<dim3(1, 256), 256>>>();
    attn_pool<<<128, 128>>>(s1_len, s2_len, S2W);
    final_mlp<<<Bq, 512>>>(mlpW, mlpb, outW, outb, out);
}

// round 14
// speedup vs baseline: 1.7989x; 1.1158x over previous
#include <cuda_runtime.h>
#include <cuda_bf16.h>
#include <cuda_fp16.h>
#include <stdint.h>
#include <math.h>

// Problem constants
#define Bq   64
#define Tq   128
#define Eq   300
#define Hq   512
#define Cq   256
#define Mq   512
#define RPS  (Bq*Tq)      // 8192
#define NROWS (2*RPS)     // 16384
#define G4H  (4*Hq)       // 2048
#define D2H  (2*Hq)       // 1024
#define NCTA 128          // 64 per direction
#define KE   304

// -------- scratch ------------------------------------------------------------
__device__ float d_xW[2][NROWS][G4H];    // gate-interleaved [(j>>1)*8 + g*2 + (j&1)]
__device__ float d_P[NROWS][Cq];
__device__ float d_r[2][Bq][D2H];
__device__ __half d_Wh16[2][G4H][Hq];                // fp16 Whh
// h state (fp16) in mma-A-fragment-major layout:
// [parity][dir][mblock(8)][ktile(32)][lane(32)][slot(4)]  (u32 = half2)
__device__ uint32_t d_h16f[2][2][8][32][32][4];
__device__ __half d_xh16[NROWS][KE];                 // fp16 gathered embeddings
__device__ __half d_Wih16[2*G4H][KE];                // fp16 Wih (both dirs)
__device__ float d_biasC[2*G4H];
__device__ __half d_Hof[NROWS][D2H];                 // fp16 Hout (attn path)
__device__ __half d_S1Wh[Cq][D2H];                   // fp16 S1W
__device__ unsigned d_flags[2][64];                  // per-CTA arrive flags
__device__ unsigned g_epoch2[2];

// ---- helpers -----------------------------------------------------------------
__device__ __forceinline__ float fsigmoid(float x) { return __fdividef(1.f, 1.f + __expf(-x)); }
__device__ __forceinline__ float ftanh(float x)    { return 1.f - __fdividef(2.f, 1.f + __expf(2.f * x)); }
__device__ __forceinline__ uint32_t pack2h(float a, float b) {
    __half2 h = __floats2half2_rn(a, b);
    return *(uint32_t*)&h;
}

// ---------------- init: flags/epoch + h0 (fp16) into frag slab ----------------
__global__ void init_state(const float* s1_h0, const float* s2_h0) {
    int idx = blockIdx.x * blockDim.x + threadIdx.x;
    if (idx < 2) g_epoch2[idx] = 0;
    if (idx < 128) d_flags[idx >> 6][idx & 63] = 0;
    if (idx >= 2 * 128 * (Hq / 2)) return;
    int jj  = idx % (Hq / 2);
    int j   = jj * 2;
    int m   = (idx / (Hq / 2)) % 128;
    int dir = idx / ((Hq / 2) * 128);
    int seq = m >> 6, b = m & 63;
    const float* h0 = seq ? s2_h0 : s1_h0;
    uint32_t v = pack2h(h0[(dir * Bq + b) * Hq + j], h0[(dir * Bq + b) * Hq + j + 1]);
    int mb   = m >> 4;
    int kt   = j >> 4;
    int lane = (m & 7) * 4 + ((j >> 1) & 3);
    int slot = ((j & 15) >> 3) * 2 + ((m & 15) >> 3);
    d_h16f[0][dir][mb][kt][lane][slot] = v;
}

// ---------------- Whh -> fp16 --------------------------------------------------
__global__ void prep_weights(const float* __restrict__ Whh_f,
                             const float* __restrict__ Whh_b) {
    int idx = blockIdx.x * blockDim.x + threadIdx.x;
    if (idx >= 2 * G4H * Hq) return;
    int dir = idx / (G4H * Hq);
    int r   = idx % (G4H * Hq);
    d_Wh16[dir][r / Hq][r % Hq] = __float2half((dir ? Whh_b : Whh_f)[r]);
}

// ---------------- gather tokens + emb -> fp16 ----------------------------------
__global__ void gather_convert(const int* __restrict__ s1, const int* __restrict__ s2,
                               const float* __restrict__ emb) {
    int idx = blockIdx.x * blockDim.x + threadIdx.x;
    if (idx >= NROWS * KE) return;
    int m = idx / KE, k = idx % KE;
    int tok = (m < RPS) ? s1[m] : s2[m - RPS];
    d_xh16[m][k] = __float2half((k < Eq) ? emb[(long)tok * Eq + k] : 0.f);
}

// ---------------- Wih (both dirs) -> fp16 + combined bias ----------------------
__global__ void convert_wih(const float* __restrict__ Wih_f, const float* __restrict__ Wih_b,
                            const float* __restrict__ b_f, const float* __restrict__ b_b) {
    int idx = blockIdx.x * blockDim.x + threadIdx.x;
    if (idx >= 2 * G4H * KE) return;
    int n = idx / KE, k = idx % KE;
    int dir = n >> 11, nn = n & 2047;
    const float* W = dir ? Wih_b : Wih_f;
    d_Wih16[n][k] = __float2half((k < Eq) ? W[(long)nn * Eq + k] : 0.f);
    if (k == 0) d_biasC[n] = (dir ? b_b : b_f)[nn];
}

// ---------------- S1W -> fp16 ---------------------------------------------------
__global__ void convert_s1w(const float* __restrict__ S1W) {
    int idx = blockIdx.x * blockDim.x + threadIdx.x;
    if (idx >= Cq * D2H) return;
    d_S1Wh[idx / D2H][idx % D2H] = __float2half(S1W[idx]);
}

// ---------------- mma.sync helper -----------------------------------------------
__device__ __forceinline__ void mma_f16(float* d, const uint32_t* a, const uint32_t* b) {
    asm volatile(
        "mma.sync.aligned.m16n8k16.row.col.f32.f16.f16.f32 "
        "{%0,%1,%2,%3}, {%4,%5,%6,%7}, {%8,%9}, {%0,%1,%2,%3};\n"
        : "+f"(d[0]), "+f"(d[1]), "+f"(d[2]), "+f"(d[3])
        : "r"(a[0]), "r"(a[1]), "r"(a[2]), "r"(a[3]),
          "r"(b[0]), "r"(b[1]));
}

// ---------------- xW via fp16 tensor cores --------------------------------------
__global__ __launch_bounds__(256)
void xw_mma() {
    const int lane = threadIdx.x & 31;
    const int warp = threadIdx.x >> 5;
    const int wm = warp & 1, wn = warp >> 1;
    const int m0 = blockIdx.y * 64 + wm * 32;
    const int n0 = blockIdx.x * 256 + wn * 64;
    const int RS = KE / 2;
    const int kc = lane & 3;
    const int rr = lane >> 2;

    const uint32_t* X = (const uint32_t*)&d_xh16[0][0];
    const uint32_t* W = (const uint32_t*)&d_Wih16[0][0];

    float acc[2][8][4] = {};

    for (int kt = 0; kt < KE / 16; ++kt) {
        const int k0 = kt * 8;
        uint32_t aF[2][4];
#pragma unroll
        for (int mt = 0; mt < 2; ++mt) {
            int base = (m0 + mt * 16 + rr) * RS + k0 + kc;
            aF[mt][0] = X[base];          aF[mt][1] = X[base + 8 * RS];
            aF[mt][2] = X[base + 4];      aF[mt][3] = X[base + 8 * RS + 4];
        }
#pragma unroll
        for (int nt = 0; nt < 8; ++nt) {
            int bb = (n0 + nt * 8 + rr) * RS + k0 + kc;
            uint32_t bF[2] = { W[bb], W[bb + 4] };
#pragma unroll
            for (int mt = 0; mt < 2; ++mt)
                mma_f16(acc[mt][nt], aF[mt], bF);
        }
    }
#pragma unroll
    for (int mt = 0; mt < 2; ++mt)
#pragma unroll
        for (int nt = 0; nt < 8; ++nt) {
            int r  = m0 + mt * 16 + rr;
            int cc = n0 + nt * 8 + (lane & 3) * 2;
#pragma unroll
            for (int i = 0; i < 4; ++i) {
                int m = r + (i >> 1) * 8;
                int n = cc + (i & 1);
                int dir = n >> 11, nn = n & 2047;
                int g = nn >> 9, j = nn & 511;
                d_xW[dir][m][(j >> 1) * 8 + g * 2 + (j & 1)] = acc[mt][nt][i] + d_biasC[n];
            }
        }
}

// ---------------- persistent LSTM: fp16 single-MMA recurrence -------------------
// 128 CTAs (64/dir). Flag-array barrier: parallel flag stores + CTA-0 aggregator.
__global__ __launch_bounds__(256)
void lstm_persist(const int* __restrict__ s1_len, const int* __restrict__ s2_len,
                  const float* __restrict__ s1_c0, const float* __restrict__ s2_c0) {
    extern __shared__ uint32_t sWf[];   // 32KB: [g(4)][kt(32)][lane(32)][b0,b1]
    const int tid  = threadIdx.x;
    const int lane = tid & 31;
    const int warp = tid >> 5;
    const int dir  = blockIdx.x & 1;
    const int cta  = blockIdx.x >> 1;   // 0..63 within dir
    const int j0   = cta * 8;

    // ---- fragment-major fp16 weight fill (once) ----
    for (int i = tid; i < 4096; i += 256) {
        int g  = i >> 10;
        int kt = (i >> 5) & 31;
        int l  = i & 31;
        int n  = l >> 2;
        int k0 = kt * 16 + (l & 3) * 2;
        const uint32_t* src = (const uint32_t*)&d_Wh16[dir][g * Hq + j0 + n][0];
        uint2 v;
        v.x = src[k0 >> 1];
        v.y = src[(k0 + 8) >> 1];
        *(uint2*)&sWf[i * 2] = v;
    }

    // ---- per-thread ownership ----
    const int m0  = warp * 16;
    const int seq = m0 >> 6;
    const int r0  = m0 + (lane >> 2);
    const int c0j = j0 + (lane & 3) * 2;
    const int*   lens = seq ? s2_len : s1_len;
    const float* c0p  = seq ? s2_c0  : s1_c0;
    const int b0 = r0 & 63;
    const int len_[2] = { lens[b0], lens[b0 + 8] };
    const int ktW   = j0 >> 4;
    const int kslot = (j0 >> 3) & 1;

    float creg[4];
#pragma unroll
    for (int ri = 0; ri < 2; ++ri)
#pragma unroll
        for (int ci = 0; ci < 2; ++ci)
            creg[ri * 2 + ci] = c0p[(dir * Bq + b0 + 8 * ri) * Hq + c0j + ci];

    __syncthreads();

    unsigned myep = 0;

    // ---- prefetch xW for step 0 ----
    int rowx_[2];
    float4 pa[2], pb[2];
#pragma unroll
    for (int ri = 0; ri < 2; ++ri) {
        int b = b0 + 8 * ri;
        int len = len_[ri];
        int tpos = dir ? (len - 1) : 0;
        rowx_[ri] = (seq * Bq + b) * Tq + tpos;
        const float4* x4 = (const float4*)&d_xW[dir][rowx_[ri]][(c0j >> 1) * 8];
        pa[ri] = __ldcs(x4);
        pb[ri] = __ldcs(x4 + 1);
    }

    for (int t = 0; t < Tq; ++t) {
        const int p = t & 1;
        const uint32_t* HF = &d_h16f[p][dir][warp][0][0][0];

        float acc[4][4] = {};
        uint32_t aF[5][4];

#define LOADA(buf, ktv) {                                                         \
        uint4 vh = __ldcg((const uint4*)(HF + (ktv) * 128 + lane * 4));           \
        aF[buf][0] = vh.x; aF[buf][1] = vh.y; aF[buf][2] = vh.z; aF[buf][3] = vh.w; }

        LOADA(0, 0); LOADA(1, 1); LOADA(2, 2); LOADA(3, 3);

#pragma unroll
        for (int kt = 0; kt < 32; ++kt) {
            const int cur = kt % 5;
            if (kt < 28) { LOADA((kt + 4) % 5, kt + 4); }
#pragma unroll
            for (int g = 0; g < 4; ++g) {
                uint2 wv = *(const uint2*)&sWf[((g * 32 + kt) * 32 + lane) * 2];
                uint32_t bF[2] = { wv.x, wv.y };
                mma_f16(acc[g], aF[cur], bF);
            }
        }
#undef LOADA

        // ---- epilogue: gates, cell/h update ----
        uint32_t hh[2];
#pragma unroll
        for (int ri = 0; ri < 2; ++ri) {
            float hv[2];
            {
                float gi = acc[0][ri * 2 + 0] + pa[ri].x;
                float gf = acc[1][ri * 2 + 0] + pa[ri].z;
                float gg = acc[2][ri * 2 + 0] + pb[ri].x;
                float go = acc[3][ri * 2 + 0] + pb[ri].z;
                float c  = fsigmoid(gf) * creg[ri * 2 + 0] + fsigmoid(gi) * ftanh(gg);
                hv[0]    = fsigmoid(go) * ftanh(c);
                creg[ri * 2 + 0] = c;
            }
            {
                float gi = acc[0][ri * 2 + 1] + pa[ri].y;
                float gf = acc[1][ri * 2 + 1] + pa[ri].w;
                float gg = acc[2][ri * 2 + 1] + pb[ri].y;
                float go = acc[3][ri * 2 + 1] + pb[ri].w;
                float c  = fsigmoid(gf) * creg[ri * 2 + 1] + fsigmoid(gi) * ftanh(gg);
                hv[1]    = fsigmoid(go) * ftanh(c);
                creg[ri * 2 + 1] = c;
            }
            hh[ri] = pack2h(hv[0], hv[1]);
        }
        // publish h state (fp16) FIRST: one STG.64
        *(uint2*)&d_h16f[p ^ 1][dir][warp][ktW][lane][kslot * 2] = make_uint2(hh[0], hh[1]);

        // ---- barrier arrive: parallel flag store (no atomic serialization) ----
        __syncthreads();
        if (tid == 0) {
            __threadfence();
            *(volatile unsigned*)&d_flags[dir][cta] = myep + 1;
        }

        // ---- overlapped with barrier: Hof (fp16, reuse packed hh) + next xW ----
#pragma unroll
        for (int ri = 0; ri < 2; ++ri)
            *(uint32_t*)&d_Hof[rowx_[ri]][dir * Hq + c0j] = hh[ri];
        int nrowx[2];
        float4 npa[2], npb[2];
        if (t + 1 < Tq) {
            const int tn = t + 1;
#pragma unroll
            for (int ri = 0; ri < 2; ++ri) {
                int b = b0 + 8 * ri;
                int len = len_[ri];
                int tpos = dir ? ((tn < len) ? (len - 1 - tn) : tn) : tn;
                nrowx[ri] = (seq * Bq + b) * Tq + tpos;
                const float4* x4 = (const float4*)&d_xW[dir][nrowx[ri]][(c0j >> 1) * 8];
                npa[ri] = __ldcs(x4);
                npb[ri] = __ldcs(x4 + 1);
            }
        }

        // ---- barrier wait ----
        if (cta == 0) {
            // aggregator: 64 threads poll the 64 flags, then release the epoch
            if (tid < 64) {
                while (*(volatile unsigned*)&d_flags[dir][tid] <= myep) { }
            }
            __syncthreads();
            if (tid == 0) {
                __threadfence();
                atomicExch(&g_epoch2[dir], myep + 1);
            }
        } else {
            if (tid == 0) {
                while (*(volatile unsigned*)&g_epoch2[dir] <= myep) { }
                __threadfence();
            }
        }
        myep++;
        __syncthreads();

        if (t + 1 < Tq) {
#pragma unroll
            for (int ri = 0; ri < 2; ++ri) {
                rowx_[ri] = nrowx[ri];
                pa[ri] = npa[ri];
                pb[ri] = npb[ri];
            }
        }
    }
}

// ---------------- attention projection: fp16 single-MMA -------------------------
__global__ __launch_bounds__(256)
void attn_mma() {
    const int lane = threadIdx.x & 31;
    const int warp = threadIdx.x >> 5;
    const int wm = warp & 1, wn = warp >> 1;
    const int m0 = blockIdx.y * 64 + wm * 32;
    const int n0 = wn * 64;
    const int RS = D2H / 2;
    const int kc = lane & 3;
    const int rr = lane >> 2;

    const uint32_t* X = (const uint32_t*)&d_Hof[0][0];
    const uint32_t* W = (const uint32_t*)&d_S1Wh[0][0];

    float acc[2][8][4] = {};

    for (int kt = 0; kt < D2H / 16; ++kt) {
        const int k0 = kt * 8;
        uint32_t aF[2][4];
#pragma unroll
        for (int mt = 0; mt < 2; ++mt) {
            int base = (m0 + mt * 16 + rr) * RS + k0 + kc;
            aF[mt][0] = X[base];          aF[mt][1] = X[base + 8 * RS];
            aF[mt][2] = X[base + 4];      aF[mt][3] = X[base + 8 * RS + 4];
        }
#pragma unroll
        for (int nt = 0; nt < 8; ++nt) {
            int bb = (n0 + nt * 8 + rr) * RS + k0 + kc;
            uint32_t bF[2] = { W[bb], W[bb + 4] };
#pragma unroll
            for (int mt = 0; mt < 2; ++mt)
                mma_f16(acc[mt][nt], aF[mt], bF);
        }
    }
#pragma unroll
    for (int mt = 0; mt < 2; ++mt)
#pragma unroll
        for (int nt = 0; nt < 8; ++nt) {
            int r  = m0 + mt * 16 + rr;
            int cc = n0 + nt * 8 + (lane & 3) * 2;
#pragma unroll
            for (int i = 0; i < 4; ++i)
                d_P[r + (i >> 1) * 8][cc + (i & 1)] = acc[mt][nt][i];
        }
}

// ---------------- masked softmax attention pooling (fp16 h) ---------------------
__global__ __launch_bounds__(128)
void attn_pool(const int* __restrict__ s1_len, const int* __restrict__ s2_len,
               const float* __restrict__ S2W) {
    __shared__ float sS2[Cq];
    __shared__ float ssc[Tq];
    __shared__ float red[Tq];
    int sb = blockIdx.x;
    int seq = sb >> 6, b = sb & 63;
    int t = threadIdx.x;
    for (int c = t; c < Cq; c += Tq) sS2[c] = S2W[c];
    __syncthreads();

    long row = (long)sb * Tq + t;
    float s = 0.f;
    for (int c = 0; c < Cq; ++c) s += ftanh(d_P[row][c]) * sS2[c];
    int len = (seq ? s2_len : s1_len)[b];
    ssc[t] = (t < len) ? s : -1e9f;
    __syncthreads();

    red[t] = ssc[t]; __syncthreads();
    for (int o = 64; o > 0; o >>= 1) { if (t < o) red[t] = fmaxf(red[t], red[t + o]); __syncthreads(); }
    float mx = red[0]; __syncthreads();
    float ex = expf(ssc[t] - mx);
    red[t] = ex; __syncthreads();
    for (int o = 64; o > 0; o >>= 1) { if (t < o) red[t] += red[t + o]; __syncthreads(); }
    float inv = 1.f / red[0];
    __syncthreads();
    ssc[t] = ex * inv;
    __syncthreads();

    long rowbase = (long)sb * Tq;
    for (int d2 = t; d2 < D2H / 2; d2 += Tq) {
        float acc0 = 0.f, acc1 = 0.f;
        for (int tt = 0; tt < Tq; ++tt) {
            long rw = rowbase + tt;
            __half2 h2 = *(const __half2*)&d_Hof[rw][d2 * 2];
            float2 hf = __half22float2(h2);
            float w = ssc[tt];
            acc0 += w * hf.x;
            acc1 += w * hf.y;
        }
        d_r[seq][b][d2 * 2]     = acc0;
        d_r[seq][b][d2 * 2 + 1] = acc1;
    }
}

// ---------------- final MLP head + sigmoid --------------------------------------
__global__ __launch_bounds__(512)
void final_mlp(const float* __restrict__ mlpW, const float* __restrict__ mlpb,
               const float* __restrict__ outW, const float* __restrict__ outb,
               float* __restrict__ out) {
    __shared__ float merged[4 * Hq];
    __shared__ float smlp[Mq];
    __shared__ float red[16];
    int b = blockIdx.x;
    int tid = threadIdx.x;

    for (int d = tid; d < 2 * D2H; d += Mq) {
        float v;
        if (d < D2H) v = d_r[0][b][d] + d_r[1][b][d];
        else { float df = d_r[0][b][d - D2H] - d_r[1][b][d - D2H]; v = df * df; }
        merged[d] = v;
    }
    __syncthreads();

    int warp = tid >> 5, lane = tid & 31;
    for (int m = warp * 32; m < warp * 32 + 32; ++m) {
        float p = 0.f;
        for (int d = lane; d < 4 * Hq; d += 32) p += merged[d] * mlpW[(long)m * 4 * Hq + d];
        for (int o = 16; o > 0; o >>= 1) p += __shfl_down_sync(0xffffffff, p, o);
        if (lane == 0) smlp[m] = p + mlpb[m];
    }
    __syncthreads();

    float p = smlp[tid] * outW[tid];
    for (int o = 16; o > 0; o >>= 1) p += __shfl_down_sync(0xffffffff, p, o);
    if (lane == 0) red[warp] = p;
    __syncthreads();
    if (tid == 0) {
        float l = outb[0];
        for (int w = 0; w < 16; ++w) l += red[w];
        out[b] = 1.f / (1.f + expf(-l));
    }
}

// ---------------- launch ----------------------------------------------------------
extern "C" void kernel_launch(void* const* d_in, const int* in_sizes, int n_in,
                              void* d_out, int out_size) {
    const int*   s1     = (const int*)d_in[0];
    const int*   s2     = (const int*)d_in[1];
    const int*   s1_len = (const int*)d_in[2];
    const int*   s2_len = (const int*)d_in[3];
    const float* s1_h0  = (const float*)d_in[4];
    const float* s1_c0  = (const float*)d_in[5];
    const float* s2_h0  = (const float*)d_in[6];
    const float* s2_c0  = (const float*)d_in[7];
    const float* emb    = (const float*)d_in[8];
    const float* Wih_f  = (const float*)d_in[9];
    const float* Whh_f  = (const float*)d_in[10];
    const float* b_f    = (const float*)d_in[11];
    const float* Wih_b  = (const float*)d_in[12];
    const float* Whh_b  = (const float*)d_in[13];
    const float* b_b    = (const float*)d_in[14];
    const float* S1W    = (const float*)d_in[15];
    const float* S2W    = (const float*)d_in[16];
    const float* mlpW   = (const float*)d_in[17];
    const float* mlpb   = (const float*)d_in[18];
    const float* outW   = (const float*)d_in[19];
    const float* outb   = (const float*)d_in[20];
    float* out = (float*)d_out;

    const int smem_lstm = 8192 * (int)sizeof(uint32_t);   // 32KB
    cudaFuncSetAttribute(lstm_persist, cudaFuncAttributeMaxDynamicSharedMemorySize, smem_lstm);

    init_state<<<(2 * 128 * (Hq / 2) + 255) / 256, 256>>>(s1_h0, s2_h0);
    prep_weights<<<(2 * G4H * Hq + 255) / 256, 256>>>(Whh_f, Whh_b);
    gather_convert<<<(NROWS * KE + 255) / 256, 256>>>(s1, s2, emb);
    convert_wih<<<(2 * G4H * KE + 255) / 256, 256>>>(Wih_f, Wih_b, b_f, b_b);
    convert_s1w<<<(Cq * D2H + 255) / 256, 256>>>(S1W);

    xw_mma<<<dim3(16, 256), 256>>>();

    lstm_persist<<<NCTA, 256, smem_lstm>>>(s1_len, s2_len, s1_c0, s2_c0);

    attn_mma<<<dim3(1, 256), 256>>>();
    attn_pool<<<128, 128>>>(s1_len, s2_len, S2W);
    final_mlp<<<Bq, 512>>>(mlpW, mlpb, outW, outb, out);
}